// round 2
// baseline (speedup 1.0000x reference)
#include <cuda_runtime.h>
#include <math.h>

#define HWSZ 16384
#define NPIX 32768
#define CC 256
#define XDIM 800
#define HID 64

// ---------------- static device scratch (no allocations allowed) ----------------
__device__ __align__(16) float g_faT[2 * HWSZ * CC];      // feat_A NHWC
__device__ __align__(16) float g_fbT[2 * HWSZ * CC];      // feat_B NHWC
__device__ __align__(16) float g_x[NPIX * XDIM];          // concat features, pixel-major (780 pad->800)
__device__ __align__(16) float g_w1t[XDIM * HID];         // enc1 weight, K-major padded
__device__ __align__(16) float g_h1[128 * HWSZ];          // raw conv outputs [b*64+c][hw]
__device__ __align__(16) float g_h2[128 * HWSZ];
__device__ __align__(16) float g_ha[128 * HWSZ];          // activated (GN+GELU)
__device__ float g_gns[128];
__device__ float g_gnt[128];

__device__ __forceinline__ float clean15(float v) {
    if (!(v == v)) return 0.f;                    // nan -> 0
    return fminf(fmaxf(v, -1.5f), 1.5f);          // +/-inf clipped too
}
__device__ __forceinline__ float geluf(float z) {
    return 0.5f * z * (1.f + erff(z * 0.70710678118654752f));
}

// ---------------- K0: NCHW -> NHWC transpose ----------------
__global__ void k_transpose(const float* __restrict__ fA, const float* __restrict__ fB) {
    __shared__ float tile[32][33];
    int z = blockIdx.z;                            // 0,1 : feat_A b0,b1 ; 2,3 : feat_B
    const float* src = (z >= 2) ? fB : fA;
    float* dst = (z >= 2) ? g_fbT : g_faT;
    int b = z & 1;
    src += (size_t)b * CC * HWSZ;
    dst += (size_t)b * HWSZ * CC;
    int hw0 = blockIdx.x * 32, c0 = blockIdx.y * 32;
    int tx = threadIdx.x, ty = threadIdx.y;        // (32,8)
#pragma unroll
    for (int i = 0; i < 32; i += 8)
        tile[ty + i][tx] = src[(c0 + ty + i) * HWSZ + hw0 + tx];
    __syncthreads();
#pragma unroll
    for (int i = 0; i < 32; i += 8)
        dst[(hw0 + ty + i) * CC + c0 + tx] = tile[tx][ty + i];
}

// ---------------- K prep: enc1 weight -> K-major padded ----------------
__global__ void k_w1t(const float* __restrict__ w1) {
    int idx = blockIdx.x * blockDim.x + threadIdx.x;
    if (idx >= XDIM * HID) return;
    int k = idx / HID, m = idx - k * HID;
    g_w1t[idx] = (k < 780) ? w1[m * 780 + k] : 0.f;
}

// ---------------- K1: per-pixel features (warp per pixel) ----------------
__global__ void __launch_bounds__(256) k_features(const float* __restrict__ cw,
                                                  const float* __restrict__ cf) {
    int p = blockIdx.x * 8 + (threadIdx.x >> 5);
    int lane = threadIdx.x & 31;
    int b = p >> 14, hw = p & 16383;
    int py = hw >> 7, px = hw & 127;

    float gx = clean15(cw[2 * p]);
    float gy = clean15(cw[2 * p + 1]);
    float xc = fmaf(gx, 64.f, 63.5f);
    float yc = fmaf(gy, 64.f, 63.5f);
    float x0f = floorf(xc), y0f = floorf(yc);
    float wx = xc - x0f, wy = yc - y0f;
    float iwx = 1.f - wx, iwy = 1.f - wy;
    int x0 = (int)x0f, y0 = (int)y0f;

    int off[4][4];
#pragma unroll
    for (int t = 0; t < 4; t++) {
        int cy = min(max(y0 - 1 + t, 0), 127);
#pragma unroll
        for (int u = 0; u < 4; u++) {
            int cx = min(max(x0 - 1 + u, 0), 127);
            off[t][u] = (((b << 14) + (cy << 7) + cx) << 8);   // *256 channels
        }
    }

    const float* fap = g_faT + ((size_t)((b << 14) | hw) << 8);
    float* xrow = g_x + (size_t)p * XDIM;

    float na = 0.f, ns[9], dt[9];
#pragma unroll
    for (int s = 0; s < 9; s++) { ns[s] = 0.f; dt[s] = 0.f; }

#pragma unroll
    for (int q = 0; q < 2; q++) {
        int c = q * 128 + lane * 4;
        float4 fa4 = *(const float4*)(fap + c);
        float fav[4] = {fa4.x, fa4.y, fa4.z, fa4.w};
        na += fav[0] * fav[0] + fav[1] * fav[1] + fav[2] * fav[2] + fav[3] * fav[3];
        *(float4*)(xrow + c) = fa4;

        float lxp[3][4];
        float wv4[4];
#pragma unroll
        for (int t = 0; t < 4; t++) {
            float4 c0v = *(const float4*)(g_fbT + off[t][0] + c);
            float4 c1v = *(const float4*)(g_fbT + off[t][1] + c);
            float4 c2v = *(const float4*)(g_fbT + off[t][2] + c);
            float4 c3v = *(const float4*)(g_fbT + off[t][3] + c);
            float cv0[4] = {c0v.x, c0v.y, c0v.z, c0v.w};
            float cv1[4] = {c1v.x, c1v.y, c1v.z, c1v.w};
            float cv2[4] = {c2v.x, c2v.y, c2v.z, c2v.w};
            float cv3[4] = {c3v.x, c3v.y, c3v.z, c3v.w};
            float lx[3][4];
#pragma unroll
            for (int j = 0; j < 4; j++) {
                lx[0][j] = cv0[j] * iwx + cv1[j] * wx;
                lx[1][j] = cv1[j] * iwx + cv2[j] * wx;
                lx[2][j] = cv2[j] * iwx + cv3[j] * wx;
            }
            if (t > 0) {
                int dyrow = t - 1;
#pragma unroll
                for (int i = 0; i < 3; i++) {
                    int s = dyrow * 3 + i;
#pragma unroll
                    for (int j = 0; j < 4; j++) {
                        float v = lxp[i][j] * iwy + lx[i][j] * wy;
                        ns[s] += v * v;
                        dt[s] += fav[j] * v;
                        if (dyrow == 1 && i == 1) wv4[j] = v;
                    }
                }
            }
#pragma unroll
            for (int i = 0; i < 3; i++)
#pragma unroll
                for (int j = 0; j < 4; j++) lxp[i][j] = lx[i][j];
        }
        float4 wout = {wv4[0], wv4[1], wv4[2], wv4[3]};
        *(float4*)(xrow + 256 + c) = wout;
        float4 ad = {fabsf(fav[0] - wv4[0]), fabsf(fav[1] - wv4[1]),
                     fabsf(fav[2] - wv4[2]), fabsf(fav[3] - wv4[3])};
        *(float4*)(xrow + 512 + c) = ad;
    }

    // warp reduce 19 values
#pragma unroll
    for (int o = 16; o; o >>= 1) {
        na += __shfl_xor_sync(0xffffffffu, na, o);
#pragma unroll
        for (int s = 0; s < 9; s++) {
            ns[s] += __shfl_xor_sync(0xffffffffu, ns[s], o);
            dt[s] += __shfl_xor_sync(0xffffffffu, dt[s], o);
        }
    }

    if (lane == 0) {
        float sna = fmaxf(sqrtf(na), 1e-12f);
        float dispx = gx - ((px + 0.5f) * (2.f / 128.f) - 1.f);
        float dispy = gy - ((py + 0.5f) * (2.f / 128.f) - 1.f);
        float cfv = cf[p];
        if (!(cfv == cfv)) cfv = 0.f;
        cfv = fminf(fmaxf(cfv, 0.f), 1.f);
        xrow[768] = dispx; xrow[769] = dispy; xrow[770] = cfv;
#pragma unroll
        for (int s = 0; s < 9; s++)
            xrow[771 + s] = dt[s] / (sna * fmaxf(sqrtf(ns[s]), 1e-12f));
#pragma unroll
        for (int k = 780; k < 800; k++) xrow[k] = 0.f;
    }
}

// ---------------- K2: enc1 as SGEMM 64 x 800 x 32768 ----------------
__global__ void __launch_bounds__(256) k_gemm1() {
    __shared__ __align__(16) float Ws[32][64];
    __shared__ __align__(16) float Xs[32][136];
    int tid = threadIdx.x;
    int pix0 = blockIdx.x * 128;
    int ty = tid >> 4, tx = tid & 15;
    int m0 = ty * 4, n0 = tx * 8;
    float acc[4][8];
#pragma unroll
    for (int j = 0; j < 4; j++)
#pragma unroll
        for (int u = 0; u < 8; u++) acc[j][u] = 0.f;

    const float* xg = g_x + (size_t)pix0 * XDIM;
    int nl = tid >> 1, kh = (tid & 1) * 16;

    for (int k0 = 0; k0 < XDIM; k0 += 32) {
        __syncthreads();
#pragma unroll
        for (int i = 0; i < 8; i++) {
            int idx = tid + i * 256;
            Ws[idx >> 6][idx & 63] = g_w1t[(k0 + (idx >> 6)) * 64 + (idx & 63)];
        }
        {
            const float* xp = xg + nl * XDIM + k0 + kh;
#pragma unroll
            for (int i = 0; i < 4; i++) {
                float4 v = *(const float4*)(xp + i * 4);
                Xs[kh + i * 4 + 0][nl] = v.x;
                Xs[kh + i * 4 + 1][nl] = v.y;
                Xs[kh + i * 4 + 2][nl] = v.z;
                Xs[kh + i * 4 + 3][nl] = v.w;
            }
        }
        __syncthreads();
#pragma unroll 8
        for (int kk = 0; kk < 32; kk++) {
            float av[4];
            av[0] = Ws[kk][m0]; av[1] = Ws[kk][m0 + 1];
            av[2] = Ws[kk][m0 + 2]; av[3] = Ws[kk][m0 + 3];
            float bv[8];
            *(float4*)&bv[0] = *(const float4*)&Xs[kk][n0];
            *(float4*)&bv[4] = *(const float4*)&Xs[kk][n0 + 4];
#pragma unroll
            for (int j = 0; j < 4; j++)
#pragma unroll
                for (int u = 0; u < 8; u++) acc[j][u] += av[j] * bv[u];
        }
    }
    int b = pix0 >> 14;
    int hwbase = pix0 & 16383;
#pragma unroll
    for (int j = 0; j < 4; j++) {
        float* op = g_h1 + (((b << 6) + m0 + j) << 14) + hwbase + n0;
        float4 v0 = {acc[j][0], acc[j][1], acc[j][2], acc[j][3]};
        float4 v1 = {acc[j][4], acc[j][5], acc[j][6], acc[j][7]};
        *(float4*)op = v0;
        *(float4*)(op + 4) = v1;
    }
}

// ---------------- GN stats -> per (b,c) scale/bias ----------------
__global__ void k_stats(int src, const float* __restrict__ gam, const float* __restrict__ bet) {
    const float* hraw = src ? g_h2 : g_h1;
    int bg = blockIdx.x;           // 0..15
    int b = bg >> 3, g = bg & 7;
    const float4* base = (const float4*)(hraw + (((b << 6) + g * 8) << 14));
    float s = 0.f, s2 = 0.f;
    for (int i = threadIdx.x; i < 32768; i += 256) {
        float4 v = base[i];
        s += v.x + v.y + v.z + v.w;
        s2 += v.x * v.x + v.y * v.y + v.z * v.z + v.w * v.w;
    }
    __shared__ float rs[256], rs2[256];
    rs[threadIdx.x] = s; rs2[threadIdx.x] = s2;
    __syncthreads();
    for (int o = 128; o; o >>= 1) {
        if (threadIdx.x < o) { rs[threadIdx.x] += rs[threadIdx.x + o]; rs2[threadIdx.x] += rs2[threadIdx.x + o]; }
        __syncthreads();
    }
    if (threadIdx.x < 8) {
        float mu = rs[0] * (1.f / 131072.f);
        float var = rs2[0] * (1.f / 131072.f) - mu * mu;
        int c = g * 8 + threadIdx.x;
        float sc = gam[c] * rsqrtf(var + 1e-5f);
        g_gns[b * 64 + c] = sc;
        g_gnt[b * 64 + c] = bet[c] - mu * sc;
    }
}

// ---------------- activation: ha = gelu(raw*s + t) ----------------
__global__ void k_act(int src) {
    const float* hraw = src ? g_h2 : g_h1;
    int i = blockIdx.x * blockDim.x + threadIdx.x;    // float4 index, 524288 total
    float4 v = ((const float4*)hraw)[i];
    int bc = i >> 12;
    float s = g_gns[bc], t = g_gnt[bc];
    v.x = geluf(v.x * s + t);
    v.y = geluf(v.y * s + t);
    v.z = geluf(v.z * s + t);
    v.w = geluf(v.w * s + t);
    ((float4*)g_ha)[i] = v;
}

// ---------------- 3x3 conv 64->64, reads g_ha, writes raw ----------------
__global__ void __launch_bounds__(256) k_conv(const float* __restrict__ wt, int outsel) {
    __shared__ float sIn[8][18][18];
    __shared__ float sW[8][576];
    float* out = outsel ? g_h2 : g_h1;
    int blk = blockIdx.x;
    int b = blk >> 6, tile = blk & 63;
    int ty0 = (tile >> 3) << 4, tx0 = (tile & 7) << 4;
    int tid = threadIdx.x;
    int og = tid >> 6;
    int t64 = tid & 63;
    int r = t64 >> 2;
    int c0 = (t64 & 3) << 2;
    float acc[16][4];
#pragma unroll
    for (int j = 0; j < 16; j++)
#pragma unroll
        for (int u = 0; u < 4; u++) acc[j][u] = 0.f;
    const float* inb = g_ha + (b << 20);

    for (int cc0 = 0; cc0 < 64; cc0 += 8) {
        __syncthreads();
        for (int idx = tid; idx < 2592; idx += 256) {
            int ci = idx / 324, rem = idx - ci * 324;
            int iy = rem / 18, ix = rem - iy * 18;
            int gy = ty0 + iy - 1, gx = tx0 + ix - 1;
            float v = 0.f;
            if (gy >= 0 && gy < 128 && gx >= 0 && gx < 128)
                v = inb[((cc0 + ci) << 14) + (gy << 7) + gx];
            sIn[ci][iy][ix] = v;
        }
        for (int idx = tid; idx < 4608; idx += 256) {
            int ci = idx / 576, rem = idx - ci * 576;
            int oc = rem / 9, tap = rem - oc * 9;
            sW[ci][rem] = wt[((oc << 6) + cc0 + ci) * 9 + tap];
        }
        __syncthreads();
#pragma unroll 1
        for (int ci = 0; ci < 8; ci++) {
            float xv[3][6];
#pragma unroll
            for (int ky = 0; ky < 3; ky++)
#pragma unroll
                for (int i = 0; i < 6; i++)
                    xv[ky][i] = sIn[ci][r + ky][c0 + i];
            const float* wp = &sW[ci][og * 144];
#pragma unroll
            for (int j = 0; j < 16; j++) {
#pragma unroll
                for (int ky = 0; ky < 3; ky++)
#pragma unroll
                    for (int kx = 0; kx < 3; kx++) {
                        float wv = wp[j * 9 + ky * 3 + kx];
#pragma unroll
                        for (int u = 0; u < 4; u++)
                            acc[j][u] += wv * xv[ky][u + kx];
                    }
            }
        }
    }
    int ocb = og << 4;
#pragma unroll
    for (int j = 0; j < 16; j++) {
        float4 v = {acc[j][0], acc[j][1], acc[j][2], acc[j][3]};
        *(float4*)(out + (((b << 6) + ocb + j) << 14) + ((ty0 + r) << 7) + tx0 + c0) = v;
    }
}

// ---------------- heads: delta(2) + conf(1) 3x3 convs + epilogue ----------------
__global__ void __launch_bounds__(256) k_heads(const float* __restrict__ dw, const float* __restrict__ db,
                                               const float* __restrict__ cwt, const float* __restrict__ cb,
                                               const float* __restrict__ warp, const float* __restrict__ conf,
                                               float* __restrict__ out) {
    __shared__ float sIn[8][18][18];
    __shared__ float sW[8][27];
    int blk = blockIdx.x;
    int b = blk >> 6, tile = blk & 63;
    int ty0 = (tile >> 3) << 4, tx0 = (tile & 7) << 4;
    int tid = threadIdx.x;
    int r = tid >> 4, cx = tid & 15;
    float a0 = 0.f, a1 = 0.f, a2 = 0.f;
    const float* inb = g_ha + (b << 20);

    for (int cc0 = 0; cc0 < 64; cc0 += 8) {
        __syncthreads();
        for (int idx = tid; idx < 2592; idx += 256) {
            int ci = idx / 324, rem = idx - ci * 324;
            int iy = rem / 18, ix = rem - iy * 18;
            int gy = ty0 + iy - 1, gx = tx0 + ix - 1;
            float v = 0.f;
            if (gy >= 0 && gy < 128 && gx >= 0 && gx < 128)
                v = inb[((cc0 + ci) << 14) + (gy << 7) + gx];
            sIn[ci][iy][ix] = v;
        }
        for (int idx = tid; idx < 216; idx += 256) {
            int ci = idx / 27, rem = idx - ci * 27;
            int oc = rem / 9, tap = rem - oc * 9;
            float v = (oc < 2) ? dw[((oc << 6) + cc0 + ci) * 9 + tap]
                               : cwt[(cc0 + ci) * 9 + tap];
            sW[ci][rem] = v;
        }
        __syncthreads();
#pragma unroll 1
        for (int ci = 0; ci < 8; ci++) {
            float x9[9];
#pragma unroll
            for (int ky = 0; ky < 3; ky++)
#pragma unroll
                for (int kx = 0; kx < 3; kx++)
                    x9[ky * 3 + kx] = sIn[ci][r + ky][cx + kx];
#pragma unroll
            for (int tap = 0; tap < 9; tap++) {
                a0 += sW[ci][tap] * x9[tap];
                a1 += sW[ci][9 + tap] * x9[tap];
                a2 += sW[ci][18 + tap] * x9[tap];
            }
        }
    }
    int hw = ((ty0 + r) << 7) + tx0 + cx;
    int p = (b << 14) + hw;
    float rx = clean15(warp[2 * p]);
    float ry = clean15(warp[2 * p + 1]);
    float fwx = fminf(fmaxf(rx + tanhf(a0 + db[0]) * 0.0625f, -1.5f), 1.5f);
    float fwy = fminf(fmaxf(ry + tanhf(a1 + db[1]) * 0.0625f, -1.5f), 1.5f);
    float cv = conf[p];
    if (!(cv == cv)) cv = 0.f;
    cv = fminf(fmaxf(cv, 0.f), 1.f);
    float pp = fminf(fmaxf(cv, 1e-4f), 1.f - 1e-4f);
    float base = logf(pp) - log1pf(-pp);
    float lg = base + 0.5f * (a2 + cb[0]);
    float rc = fminf(fmaxf(1.f / (1.f + expf(-lg)), 0.f), 1.f);
    out[2 * p] = fwx;
    out[2 * p + 1] = fwy;
    out[65536 + p] = rc;
    out[98304 + p] = lg;
}

extern "C" void kernel_launch(void* const* d_in, const int* in_sizes, int n_in,
                              void* d_out, int out_size) {
    (void)in_sizes; (void)n_in; (void)out_size;
    const float* fA  = (const float*)d_in[0];
    const float* fB  = (const float*)d_in[1];
    const float* cw  = (const float*)d_in[2];
    const float* cf  = (const float*)d_in[3];
    const float* e1w = (const float*)d_in[4];
    const float* g1g = (const float*)d_in[5];
    const float* g1b = (const float*)d_in[6];
    const float* e2w = (const float*)d_in[7];
    const float* g2g = (const float*)d_in[8];
    const float* g2b = (const float*)d_in[9];
    const float* e3w = (const float*)d_in[10];
    const float* g3g = (const float*)d_in[11];
    const float* g3b = (const float*)d_in[12];
    const float* dw  = (const float*)d_in[13];
    const float* db  = (const float*)d_in[14];
    const float* cwt = (const float*)d_in[15];
    const float* cb  = (const float*)d_in[16];
    float* out = (float*)d_out;

    k_transpose<<<dim3(512, 8, 4), dim3(32, 8)>>>(fA, fB);
    k_w1t<<<200, 256>>>(e1w);
    k_features<<<4096, 256>>>(cw, cf);
    k_gemm1<<<256, 256>>>();
    k_stats<<<16, 256>>>(0, g1g, g1b);
    k_act<<<2048, 256>>>(0);
    k_conv<<<128, 256>>>(e2w, 1);
    k_stats<<<16, 256>>>(1, g2g, g2b);
    k_act<<<2048, 256>>>(1);
    k_conv<<<128, 256>>>(e3w, 0);
    k_stats<<<16, 256>>>(0, g3g, g3b);
    k_act<<<2048, 256>>>(0);
    k_heads<<<128, 256>>>(dw, db, cwt, cb, cw, cf, out);
}

// round 3
// speedup vs baseline: 1.0748x; 1.0748x over previous
#include <cuda_runtime.h>
#include <math.h>

#define HWSZ 16384
#define NPIX 32768
#define CC 256
#define XDIM 800
#define HID 64

// ---------------- static device scratch (no allocations allowed) ----------------
__device__ __align__(16) float g_faT[2 * HWSZ * CC];      // feat_A NHWC
__device__ __align__(16) float g_fbT[2 * HWSZ * CC];      // feat_B NHWC
__device__ __align__(16) float g_x[NPIX * XDIM];          // concat features, pixel-major (780 pad->800)
__device__ __align__(16) float g_w1t[XDIM * HID];         // enc1 weight, K-major padded
__device__ __align__(16) float g_h1[128 * HWSZ];          // raw layer outputs [b*64+c][hw]
__device__ __align__(16) float g_h2[128 * HWSZ];
__device__ float g_gns[128];
__device__ float g_gnt[128];
__device__ float2 g_part[16][8];

__device__ __forceinline__ float clean15(float v) {
    if (!(v == v)) return 0.f;
    return fminf(fmaxf(v, -1.5f), 1.5f);
}
__device__ __forceinline__ float geluf(float z) {
    return 0.5f * z * (1.f + erff(z * 0.70710678118654752f));
}

// ---------------- K0: NCHW -> NHWC transpose ----------------
__global__ void k_transpose(const float* __restrict__ fA, const float* __restrict__ fB) {
    __shared__ float tile[32][33];
    int z = blockIdx.z;
    const float* src = (z >= 2) ? fB : fA;
    float* dst = (z >= 2) ? g_fbT : g_faT;
    int b = z & 1;
    src += (size_t)b * CC * HWSZ;
    dst += (size_t)b * HWSZ * CC;
    int hw0 = blockIdx.x * 32, c0 = blockIdx.y * 32;
    int tx = threadIdx.x, ty = threadIdx.y;
#pragma unroll
    for (int i = 0; i < 32; i += 8)
        tile[ty + i][tx] = src[(c0 + ty + i) * HWSZ + hw0 + tx];
    __syncthreads();
#pragma unroll
    for (int i = 0; i < 32; i += 8)
        dst[(hw0 + ty + i) * CC + c0 + tx] = tile[tx][ty + i];
}

// ---------------- enc1 weight -> K-major padded ----------------
__global__ void k_w1t(const float* __restrict__ w1) {
    int idx = blockIdx.x * blockDim.x + threadIdx.x;
    if (idx >= XDIM * HID) return;
    int k = idx / HID, m = idx - k * HID;
    g_w1t[idx] = (k < 780) ? w1[m * 780 + k] : 0.f;
}

// ---------------- K1: per-pixel features (warp per pixel) ----------------
__global__ void __launch_bounds__(256) k_features(const float* __restrict__ cw,
                                                  const float* __restrict__ cf) {
    int p = blockIdx.x * 8 + (threadIdx.x >> 5);
    int lane = threadIdx.x & 31;
    int b = p >> 14, hw = p & 16383;
    int py = hw >> 7, px = hw & 127;

    float gx = clean15(cw[2 * p]);
    float gy = clean15(cw[2 * p + 1]);
    float xc = fmaf(gx, 64.f, 63.5f);
    float yc = fmaf(gy, 64.f, 63.5f);
    float x0f = floorf(xc), y0f = floorf(yc);
    float wx = xc - x0f, wy = yc - y0f;
    float iwx = 1.f - wx, iwy = 1.f - wy;
    int x0 = (int)x0f, y0 = (int)y0f;

    int off[4][4];
#pragma unroll
    for (int t = 0; t < 4; t++) {
        int cy = min(max(y0 - 1 + t, 0), 127);
#pragma unroll
        for (int u = 0; u < 4; u++) {
            int cx = min(max(x0 - 1 + u, 0), 127);
            off[t][u] = (((b << 14) + (cy << 7) + cx) << 8);
        }
    }

    const float* fap = g_faT + ((size_t)((b << 14) | hw) << 8);
    float* xrow = g_x + (size_t)p * XDIM;

    float na = 0.f, ns[9], dt[9];
#pragma unroll
    for (int s = 0; s < 9; s++) { ns[s] = 0.f; dt[s] = 0.f; }

#pragma unroll
    for (int q = 0; q < 2; q++) {
        int c = q * 128 + lane * 4;
        float4 fa4 = *(const float4*)(fap + c);
        float fav[4] = {fa4.x, fa4.y, fa4.z, fa4.w};
        na += fav[0] * fav[0] + fav[1] * fav[1] + fav[2] * fav[2] + fav[3] * fav[3];
        *(float4*)(xrow + c) = fa4;

        float lxp[3][4];
        float wv4[4];
#pragma unroll
        for (int t = 0; t < 4; t++) {
            float4 c0v = *(const float4*)(g_fbT + off[t][0] + c);
            float4 c1v = *(const float4*)(g_fbT + off[t][1] + c);
            float4 c2v = *(const float4*)(g_fbT + off[t][2] + c);
            float4 c3v = *(const float4*)(g_fbT + off[t][3] + c);
            float cv0[4] = {c0v.x, c0v.y, c0v.z, c0v.w};
            float cv1[4] = {c1v.x, c1v.y, c1v.z, c1v.w};
            float cv2[4] = {c2v.x, c2v.y, c2v.z, c2v.w};
            float cv3[4] = {c3v.x, c3v.y, c3v.z, c3v.w};
            float lx[3][4];
#pragma unroll
            for (int j = 0; j < 4; j++) {
                lx[0][j] = cv0[j] * iwx + cv1[j] * wx;
                lx[1][j] = cv1[j] * iwx + cv2[j] * wx;
                lx[2][j] = cv2[j] * iwx + cv3[j] * wx;
            }
            if (t > 0) {
                int dyrow = t - 1;
#pragma unroll
                for (int i = 0; i < 3; i++) {
                    int s = dyrow * 3 + i;
#pragma unroll
                    for (int j = 0; j < 4; j++) {
                        float v = lxp[i][j] * iwy + lx[i][j] * wy;
                        ns[s] += v * v;
                        dt[s] += fav[j] * v;
                        if (dyrow == 1 && i == 1) wv4[j] = v;
                    }
                }
            }
#pragma unroll
            for (int i = 0; i < 3; i++)
#pragma unroll
                for (int j = 0; j < 4; j++) lxp[i][j] = lx[i][j];
        }
        float4 wout = {wv4[0], wv4[1], wv4[2], wv4[3]};
        *(float4*)(xrow + 256 + c) = wout;
        float4 ad = {fabsf(fav[0] - wv4[0]), fabsf(fav[1] - wv4[1]),
                     fabsf(fav[2] - wv4[2]), fabsf(fav[3] - wv4[3])};
        *(float4*)(xrow + 512 + c) = ad;
    }

#pragma unroll
    for (int o = 16; o; o >>= 1) {
        na += __shfl_xor_sync(0xffffffffu, na, o);
#pragma unroll
        for (int s = 0; s < 9; s++) {
            ns[s] += __shfl_xor_sync(0xffffffffu, ns[s], o);
            dt[s] += __shfl_xor_sync(0xffffffffu, dt[s], o);
        }
    }

    if (lane == 0) {
        float sna = fmaxf(sqrtf(na), 1e-12f);
        float dispx = gx - ((px + 0.5f) * (2.f / 128.f) - 1.f);
        float dispy = gy - ((py + 0.5f) * (2.f / 128.f) - 1.f);
        float cfv = cf[p];
        if (!(cfv == cfv)) cfv = 0.f;
        cfv = fminf(fmaxf(cfv, 0.f), 1.f);
        xrow[768] = dispx; xrow[769] = dispy; xrow[770] = cfv;
#pragma unroll
        for (int s = 0; s < 9; s++)
            xrow[771 + s] = dt[s] / (sna * fmaxf(sqrtf(ns[s]), 1e-12f));
#pragma unroll
        for (int k = 780; k < 800; k++) xrow[k] = 0.f;
    }
}

// ---------------- K2: enc1 SGEMM 64 x 800 x 32768, warp-uniform M ----------------
__global__ void __launch_bounds__(256) k_gemm1() {
    __shared__ __align__(16) float Ws[32 * 64];
    __shared__ __align__(16) float Xs[32 * 132];
    int tid = threadIdx.x;
    int pix0 = blockIdx.x * 128;
    int ty = tid >> 5, tx = tid & 31;      // warp-uniform m-group
    int m0 = ty * 8, n0 = tx * 4;
    float acc[8][4];
#pragma unroll
    for (int j = 0; j < 8; j++)
#pragma unroll
        for (int u = 0; u < 4; u++) acc[j][u] = 0.f;

    const float* xg = g_x + (size_t)pix0 * XDIM;
    int nl = tid >> 1, kh = (tid & 1) * 16;

    for (int k0 = 0; k0 < XDIM; k0 += 32) {
        __syncthreads();
        ((float4*)Ws)[tid] = ((const float4*)(g_w1t + k0 * 64))[tid];
        ((float4*)Ws)[tid + 256] = ((const float4*)(g_w1t + k0 * 64))[tid + 256];
        {
            const float* xp = xg + nl * XDIM + k0 + kh;
#pragma unroll
            for (int i = 0; i < 4; i++) {
                float4 v = *(const float4*)(xp + i * 4);
                Xs[(kh + i * 4 + 0) * 132 + nl] = v.x;
                Xs[(kh + i * 4 + 1) * 132 + nl] = v.y;
                Xs[(kh + i * 4 + 2) * 132 + nl] = v.z;
                Xs[(kh + i * 4 + 3) * 132 + nl] = v.w;
            }
        }
        __syncthreads();
#pragma unroll 8
        for (int kk = 0; kk < 32; kk++) {
            float4 a0 = *(const float4*)&Ws[kk * 64 + m0];      // broadcast across warp
            float4 a1 = *(const float4*)&Ws[kk * 64 + m0 + 4];
            float4 bv = *(const float4*)&Xs[kk * 132 + n0];
            float av[8] = {a0.x, a0.y, a0.z, a0.w, a1.x, a1.y, a1.z, a1.w};
            float bb[4] = {bv.x, bv.y, bv.z, bv.w};
#pragma unroll
            for (int j = 0; j < 8; j++)
#pragma unroll
                for (int u = 0; u < 4; u++) acc[j][u] += av[j] * bb[u];
        }
    }
    int b = pix0 >> 14;
    int hwbase = pix0 & 16383;
#pragma unroll
    for (int j = 0; j < 8; j++) {
        float4 v = {acc[j][0], acc[j][1], acc[j][2], acc[j][3]};
        *(float4*)(g_h1 + (((b << 6) + m0 + j) << 14) + hwbase + n0) = v;
    }
}

// ---------------- GN stats, two-stage ----------------
__global__ void k_stats1(int src) {
    const float* hraw = src ? g_h2 : g_h1;
    int bg = blockIdx.x >> 3, slice = blockIdx.x & 7;
    // group data is contiguous: 8 channels * 16384 = 131072 floats
    const float4* base = (const float4*)(hraw + (size_t)bg * 131072 + (size_t)slice * 16384);
    float s = 0.f, s2 = 0.f;
    for (int i = threadIdx.x; i < 4096; i += 256) {
        float4 v = base[i];
        s += v.x + v.y + v.z + v.w;
        s2 += v.x * v.x + v.y * v.y + v.z * v.z + v.w * v.w;
    }
    __shared__ float rs[256], rs2[256];
    rs[threadIdx.x] = s; rs2[threadIdx.x] = s2;
    __syncthreads();
    for (int o = 128; o; o >>= 1) {
        if (threadIdx.x < o) { rs[threadIdx.x] += rs[threadIdx.x + o]; rs2[threadIdx.x] += rs2[threadIdx.x + o]; }
        __syncthreads();
    }
    if (threadIdx.x == 0) g_part[bg][slice] = make_float2(rs[0], rs2[0]);
}

__global__ void k_stats2(const float* __restrict__ gam, const float* __restrict__ bet) {
    int tid = threadIdx.x;            // 128 threads: bg = tid>>3, c8 = tid&7
    int bg = tid >> 3, c8 = tid & 7;
    float s = 0.f, s2 = 0.f;
#pragma unroll
    for (int i = 0; i < 8; i++) { float2 v = g_part[bg][i]; s += v.x; s2 += v.y; }
    float mu = s * (1.f / 131072.f);
    float var = s2 * (1.f / 131072.f) - mu * mu;
    int b = bg >> 3, g = bg & 7;
    int c = g * 8 + c8;
    float sc = gam[c] * rsqrtf(var + 1e-5f);
    g_gns[b * 64 + c] = sc;
    g_gnt[b * 64 + c] = bet[c] - mu * sc;
}

// ---------------- 3x3 conv 64->64, GN+GELU folded into input load ----------------
__global__ void __launch_bounds__(256) k_conv(const float* __restrict__ wt, int srcsel, int dstsel) {
    __shared__ float sIn[8][18][19];
    __shared__ float sW[8][9][64];
    const float* src = srcsel ? g_h2 : g_h1;
    float* dst = dstsel ? g_h2 : g_h1;
    int blk = blockIdx.x;
    int b = blk >> 6, tile = blk & 63;
    int ty0 = (tile >> 3) << 4, tx0 = (tile & 7) << 4;
    int tid = threadIdx.x;
    int og = tid >> 5;                 // warp-uniform oc group (8 oc)
    int t32 = tid & 31;
    int r = t32 >> 1;                  // 0..15 row in tile
    int c0 = (t32 & 1) << 3;           // 0 or 8
    float acc[8][8];
#pragma unroll
    for (int j = 0; j < 8; j++)
#pragma unroll
        for (int u = 0; u < 8; u++) acc[j][u] = 0.f;
    const float* inb = src + ((size_t)b << 20);

    for (int cc0 = 0; cc0 < 64; cc0 += 8) {
        __syncthreads();
        for (int idx = tid; idx < 2592; idx += 256) {
            int ci = idx / 324, rem = idx - ci * 324;
            int iy = rem / 18, ix = rem - iy * 18;
            int gy = ty0 + iy - 1, gx = tx0 + ix - 1;
            float v = 0.f;
            if (gy >= 0 && gy < 128 && gx >= 0 && gx < 128) {
                float raw = inb[((cc0 + ci) << 14) + (gy << 7) + gx];
                int bc = (b << 6) + cc0 + ci;
                v = geluf(fmaf(raw, g_gns[bc], g_gnt[bc]));
            }
            sIn[ci][iy][ix] = v;
        }
        for (int idx = tid; idx < 4608; idx += 256) {
            int ci = idx / 576, rem = idx - ci * 576;
            int tap = rem >> 6, oc = rem & 63;
            sW[ci][tap][oc] = wt[((oc << 6) + cc0 + ci) * 9 + tap];
        }
        __syncthreads();
#pragma unroll 1
        for (int ci = 0; ci < 8; ci++) {
            float xv[3][10];
#pragma unroll
            for (int ky = 0; ky < 3; ky++)
#pragma unroll
                for (int i = 0; i < 10; i++)
                    xv[ky][i] = sIn[ci][r + ky][c0 + i];
#pragma unroll
            for (int ky = 0; ky < 3; ky++)
#pragma unroll
                for (int kx = 0; kx < 3; kx++) {
                    float4 w0 = *(const float4*)&sW[ci][ky * 3 + kx][og * 8];       // broadcast
                    float4 w1 = *(const float4*)&sW[ci][ky * 3 + kx][og * 8 + 4];
                    float wv[8] = {w0.x, w0.y, w0.z, w0.w, w1.x, w1.y, w1.z, w1.w};
#pragma unroll
                    for (int j = 0; j < 8; j++)
#pragma unroll
                        for (int u = 0; u < 8; u++)
                            acc[j][u] += wv[j] * xv[ky][u + kx];
                }
        }
    }
    int ocb = og << 3;
#pragma unroll
    for (int j = 0; j < 8; j++) {
        float4 v0 = {acc[j][0], acc[j][1], acc[j][2], acc[j][3]};
        float4 v1 = {acc[j][4], acc[j][5], acc[j][6], acc[j][7]};
        float* op = dst + (((b << 6) + ocb + j) << 14) + ((ty0 + r) << 7) + tx0 + c0;
        *(float4*)op = v0;
        *(float4*)(op + 4) = v1;
    }
}

// ---------------- heads: delta(2)+conf(1) convs + epilogue, GN+GELU folded ----------------
__global__ void __launch_bounds__(256) k_heads(const float* __restrict__ dw, const float* __restrict__ db,
                                               const float* __restrict__ cwt, const float* __restrict__ cb,
                                               const float* __restrict__ warp, const float* __restrict__ conf,
                                               float* __restrict__ out) {
    __shared__ float sIn[8][18][19];
    __shared__ float sW[8][27];
    int blk = blockIdx.x;
    int b = blk >> 6, tile = blk & 63;
    int ty0 = (tile >> 3) << 4, tx0 = (tile & 7) << 4;
    int tid = threadIdx.x;
    int r = tid >> 4, cx = tid & 15;
    float a0 = 0.f, a1 = 0.f, a2 = 0.f;
    const float* inb = g_h1 + ((size_t)b << 20);

    for (int cc0 = 0; cc0 < 64; cc0 += 8) {
        __syncthreads();
        for (int idx = tid; idx < 2592; idx += 256) {
            int ci = idx / 324, rem = idx - ci * 324;
            int iy = rem / 18, ix = rem - iy * 18;
            int gy = ty0 + iy - 1, gx = tx0 + ix - 1;
            float v = 0.f;
            if (gy >= 0 && gy < 128 && gx >= 0 && gx < 128) {
                float raw = inb[((cc0 + ci) << 14) + (gy << 7) + gx];
                int bc = (b << 6) + cc0 + ci;
                v = geluf(fmaf(raw, g_gns[bc], g_gnt[bc]));
            }
            sIn[ci][iy][ix] = v;
        }
        for (int idx = tid; idx < 216; idx += 256) {
            int ci = idx / 27, rem = idx - ci * 27;
            int oc = rem / 9, tap = rem - oc * 9;
            float v = (oc < 2) ? dw[((oc << 6) + cc0 + ci) * 9 + tap]
                               : cwt[(cc0 + ci) * 9 + tap];
            sW[ci][rem] = v;
        }
        __syncthreads();
#pragma unroll 1
        for (int ci = 0; ci < 8; ci++) {
            float x9[9];
#pragma unroll
            for (int ky = 0; ky < 3; ky++)
#pragma unroll
                for (int kx = 0; kx < 3; kx++)
                    x9[ky * 3 + kx] = sIn[ci][r + ky][cx + kx];
#pragma unroll
            for (int tap = 0; tap < 9; tap++) {
                a0 += sW[ci][tap] * x9[tap];
                a1 += sW[ci][9 + tap] * x9[tap];
                a2 += sW[ci][18 + tap] * x9[tap];
            }
        }
    }
    int hw = ((ty0 + r) << 7) + tx0 + cx;
    int p = (b << 14) + hw;
    float rx = clean15(warp[2 * p]);
    float ry = clean15(warp[2 * p + 1]);
    float fwx = fminf(fmaxf(rx + tanhf(a0 + db[0]) * 0.0625f, -1.5f), 1.5f);
    float fwy = fminf(fmaxf(ry + tanhf(a1 + db[1]) * 0.0625f, -1.5f), 1.5f);
    float cv = conf[p];
    if (!(cv == cv)) cv = 0.f;
    cv = fminf(fmaxf(cv, 0.f), 1.f);
    float pp = fminf(fmaxf(cv, 1e-4f), 1.f - 1e-4f);
    float base = logf(pp) - log1pf(-pp);
    float lg = base + 0.5f * (a2 + cb[0]);
    float rc = fminf(fmaxf(1.f / (1.f + expf(-lg)), 0.f), 1.f);
    out[2 * p] = fwx;
    out[2 * p + 1] = fwy;
    out[65536 + p] = rc;
    out[98304 + p] = lg;
}

extern "C" void kernel_launch(void* const* d_in, const int* in_sizes, int n_in,
                              void* d_out, int out_size) {
    (void)in_sizes; (void)n_in; (void)out_size;
    const float* fA  = (const float*)d_in[0];
    const float* fB  = (const float*)d_in[1];
    const float* cw  = (const float*)d_in[2];
    const float* cf  = (const float*)d_in[3];
    const float* e1w = (const float*)d_in[4];
    const float* g1g = (const float*)d_in[5];
    const float* g1b = (const float*)d_in[6];
    const float* e2w = (const float*)d_in[7];
    const float* g2g = (const float*)d_in[8];
    const float* g2b = (const float*)d_in[9];
    const float* e3w = (const float*)d_in[10];
    const float* g3g = (const float*)d_in[11];
    const float* g3b = (const float*)d_in[12];
    const float* dw  = (const float*)d_in[13];
    const float* db  = (const float*)d_in[14];
    const float* cwt = (const float*)d_in[15];
    const float* cb  = (const float*)d_in[16];
    float* out = (float*)d_out;

    k_transpose<<<dim3(512, 8, 4), dim3(32, 8)>>>(fA, fB);
    k_w1t<<<200, 256>>>(e1w);
    k_features<<<4096, 256>>>(cw, cf);
    k_gemm1<<<256, 256>>>();
    k_stats1<<<128, 256>>>(0);
    k_stats2<<<1, 128>>>(g1g, g1b);
    k_conv<<<128, 256>>>(e2w, 0, 1);
    k_stats1<<<128, 256>>>(1);
    k_stats2<<<1, 128>>>(g2g, g2b);
    k_conv<<<128, 256>>>(e3w, 1, 0);
    k_stats1<<<128, 256>>>(0);
    k_stats2<<<1, 128>>>(g3g, g3b);
    k_heads<<<128, 256>>>(dw, db, cwt, cb, cw, cf, out);
}

// round 5
// speedup vs baseline: 2.5087x; 2.3341x over previous
#include <cuda_runtime.h>
#include <cuda_bf16.h>
#include <math.h>
#include <stdint.h>

#define HWSZ 16384
#define NPIX 32768
#define CC 256

// ---------------- static device scratch ----------------
__device__ __align__(16) __nv_bfloat16 g_faT[2 * HWSZ * CC];     // feat_A NHWC bf16
__device__ __align__(16) __nv_bfloat16 g_fbT[2 * HWSZ * CC];     // feat_B NHWC bf16
__device__ __align__(16) __nv_bfloat16 g_xb[(size_t)NPIX * 832]; // X features bf16 (780 pad->832)
__device__ __align__(16) __nv_bfloat16 g_w1k[13 * 4096];         // enc1 W [chunk][oc][k64]
__device__ __align__(16) __nv_bfloat16 g_wck[2][9 * 4096];       // conv W [tap][oc][ci]
__device__ __align__(16) float g_h[(size_t)NPIX * 64];           // raw layer out, NHWC fp32
__device__ __align__(16) __nv_bfloat16 g_ab[(size_t)NPIX * 64];  // activated NHWC bf16
__device__ float g_gns[128];
__device__ float g_gnt[128];
__device__ float g_pcs[2 * 16 * 64];
__device__ float g_pcs2[2 * 16 * 64];

__device__ __forceinline__ float clean15(float v) {
    if (!(v == v)) return 0.f;
    return fminf(fmaxf(v, -1.5f), 1.5f);
}
__device__ __forceinline__ float geluf(float z) {
    return 0.5f * z * (1.f + erff(z * 0.70710678118654752f));
}

// bf16 HMMA: D(16x8,f32) += A(16x16,bf16) * B(8x16,bf16)^T
__device__ __forceinline__ void mma16816(float* d, const uint32_t* a, const uint32_t* b) {
    asm volatile(
        "mma.sync.aligned.m16n8k16.row.col.f32.bf16.bf16.f32 "
        "{%0,%1,%2,%3}, {%4,%5,%6,%7}, {%8,%9}, {%0,%1,%2,%3};"
        : "+f"(d[0]), "+f"(d[1]), "+f"(d[2]), "+f"(d[3])
        : "r"(a[0]), "r"(a[1]), "r"(a[2]), "r"(a[3]), "r"(b[0]), "r"(b[1]));
}

// ---------------- K0: NCHW fp32 -> NHWC bf16 transpose ----------------
__global__ void k_transpose(const float* __restrict__ fA, const float* __restrict__ fB) {
    __shared__ float tile[32][33];
    int z = blockIdx.z;
    const float* src = (z >= 2) ? fB : fA;
    __nv_bfloat16* dst = (z >= 2) ? g_fbT : g_faT;
    int b = z & 1;
    src += (size_t)b * CC * HWSZ;
    dst += (size_t)b * HWSZ * CC;
    int hw0 = blockIdx.x * 32, c0 = blockIdx.y * 32;
    int tx = threadIdx.x, ty = threadIdx.y;
#pragma unroll
    for (int i = 0; i < 32; i += 8)
        tile[ty + i][tx] = src[(c0 + ty + i) * HWSZ + hw0 + tx];
    __syncthreads();
#pragma unroll
    for (int i = 0; i < 32; i += 8)
        dst[(size_t)(hw0 + ty + i) * CC + c0 + tx] = __float2bfloat16(tile[tx][ty + i]);
}

// ---------------- weight prep ----------------
__global__ void k_w1k(const float* __restrict__ w1) {
    int idx = blockIdx.x * blockDim.x + threadIdx.x;
    if (idx >= 13 * 4096) return;
    int chunk = idx >> 12, rem = idx & 4095;
    int oc = rem >> 6, k = rem & 63;
    int kg = chunk * 64 + k;
    g_w1k[idx] = __float2bfloat16((kg < 780) ? w1[oc * 780 + kg] : 0.f);
}
__global__ void k_wck(const float* __restrict__ w, int which) {
    int idx = blockIdx.x * blockDim.x + threadIdx.x;
    if (idx >= 9 * 4096) return;
    int tap = idx >> 12, rem = idx & 4095;
    int oc = rem >> 6, ci = rem & 63;
    g_wck[which][idx] = __float2bfloat16(w[(oc * 64 + ci) * 9 + tap]);
}

// ---------------- K1: per-pixel features (warp per pixel), bf16 in/out ----------------
__global__ void __launch_bounds__(256) k_features(const float* __restrict__ cw,
                                                  const float* __restrict__ cf) {
    int p = blockIdx.x * 8 + (threadIdx.x >> 5);
    int lane = threadIdx.x & 31;
    int b = p >> 14, hw = p & 16383;
    int py = hw >> 7, px = hw & 127;

    float gx = clean15(cw[2 * p]);
    float gy = clean15(cw[2 * p + 1]);
    float xc = fmaf(gx, 64.f, 63.5f);
    float yc = fmaf(gy, 64.f, 63.5f);
    float x0f = floorf(xc), y0f = floorf(yc);
    float wx = xc - x0f, wy = yc - y0f;
    float iwx = 1.f - wx, iwy = 1.f - wy;
    int x0 = (int)x0f, y0 = (int)y0f;

    int off[4][4];
#pragma unroll
    for (int t = 0; t < 4; t++) {
        int cyp = min(max(y0 - 1 + t, 0), 127);
#pragma unroll
        for (int u = 0; u < 4; u++) {
            int cxp = min(max(x0 - 1 + u, 0), 127);
            off[t][u] = (((b << 14) + (cyp << 7) + cxp) << 8);
        }
    }

    const __nv_bfloat16* fap = g_faT + ((size_t)((b << 14) | hw) << 8);
    __nv_bfloat16* xrow = g_xb + (size_t)p * 832;
    int c = lane * 8;

    uint4 faU = *(const uint4*)(fap + c);
    float fav[8];
    {
        const __nv_bfloat162* h = (const __nv_bfloat162*)&faU;
#pragma unroll
        for (int j = 0; j < 4; j++) {
            float2 f = __bfloat1622float2(h[j]);
            fav[2 * j] = f.x; fav[2 * j + 1] = f.y;
        }
    }
    float na = 0.f, ns[9], dt[9];
#pragma unroll
    for (int s = 0; s < 9; s++) { ns[s] = 0.f; dt[s] = 0.f; }
#pragma unroll
    for (int j = 0; j < 8; j++) na += fav[j] * fav[j];
    *(uint4*)(xrow + c) = faU;

    float lxp[3][8];
    float wv[8];
#pragma unroll
    for (int t = 0; t < 4; t++) {
        float cv[4][8];
#pragma unroll
        for (int u = 0; u < 4; u++) {
            uint4 U = *(const uint4*)(g_fbT + off[t][u] + c);
            const __nv_bfloat162* h = (const __nv_bfloat162*)&U;
#pragma unroll
            for (int j = 0; j < 4; j++) {
                float2 f = __bfloat1622float2(h[j]);
                cv[u][2 * j] = f.x; cv[u][2 * j + 1] = f.y;
            }
        }
        float lx[3][8];
#pragma unroll
        for (int j = 0; j < 8; j++) {
            lx[0][j] = cv[0][j] * iwx + cv[1][j] * wx;
            lx[1][j] = cv[1][j] * iwx + cv[2][j] * wx;
            lx[2][j] = cv[2][j] * iwx + cv[3][j] * wx;
        }
        if (t > 0) {
            int dyrow = t - 1;
#pragma unroll
            for (int i = 0; i < 3; i++) {
                int s = dyrow * 3 + i;
#pragma unroll
                for (int j = 0; j < 8; j++) {
                    float v = lxp[i][j] * iwy + lx[i][j] * wy;
                    ns[s] += v * v;
                    dt[s] += fav[j] * v;
                    if (dyrow == 1 && i == 1) wv[j] = v;
                }
            }
        }
#pragma unroll
        for (int i = 0; i < 3; i++)
#pragma unroll
            for (int j = 0; j < 8; j++) lxp[i][j] = lx[i][j];
    }
    {
        uint4 W, D;
        __nv_bfloat162* wh = (__nv_bfloat162*)&W;
        __nv_bfloat162* dh = (__nv_bfloat162*)&D;
#pragma unroll
        for (int j = 0; j < 4; j++) {
            wh[j] = __floats2bfloat162_rn(wv[2 * j], wv[2 * j + 1]);
            dh[j] = __floats2bfloat162_rn(fabsf(fav[2 * j] - wv[2 * j]),
                                          fabsf(fav[2 * j + 1] - wv[2 * j + 1]));
        }
        *(uint4*)(xrow + 256 + c) = W;
        *(uint4*)(xrow + 512 + c) = D;
    }

#pragma unroll
    for (int o = 16; o; o >>= 1) {
        na += __shfl_xor_sync(0xffffffffu, na, o);
#pragma unroll
        for (int s = 0; s < 9; s++) {
            ns[s] += __shfl_xor_sync(0xffffffffu, ns[s], o);
            dt[s] += __shfl_xor_sync(0xffffffffu, dt[s], o);
        }
    }
    if (lane == 0) {
        float sna = fmaxf(sqrtf(na), 1e-12f);
        float dispx = gx - ((px + 0.5f) * (2.f / 128.f) - 1.f);
        float dispy = gy - ((py + 0.5f) * (2.f / 128.f) - 1.f);
        float cfv = cf[p];
        if (!(cfv == cfv)) cfv = 0.f;
        cfv = fminf(fmaxf(cfv, 0.f), 1.f);
        xrow[768] = __float2bfloat16(dispx);
        xrow[769] = __float2bfloat16(dispy);
        xrow[770] = __float2bfloat16(cfv);
#pragma unroll
        for (int s = 0; s < 9; s++)
            xrow[771 + s] = __float2bfloat16(dt[s] / (sna * fmaxf(sqrtf(ns[s]), 1e-12f)));
    } else if (lane <= 13) {
        ((uint2*)(xrow + 780))[lane - 1] = make_uint2(0u, 0u);   // zero pad 780..831
    }
}

// ---------------- enc1 GEMM via mma.sync: 128 px x 64 oc per CTA, K=832 ----------------
__global__ void __launch_bounds__(256) k_gemm1_mma() {
    __shared__ __align__(16) __nv_bfloat16 As[128 * 72];
    __shared__ __align__(16) __nv_bfloat16 Bs[64 * 72];
    int tid = threadIdx.x;
    int warp = tid >> 5, lane = tid & 31;
    int g = lane >> 2, t = lane & 3;
    int wm = warp & 3, wn = warp >> 2;
    float acc[2][4][4];
#pragma unroll
    for (int mt = 0; mt < 2; mt++)
#pragma unroll
        for (int nt = 0; nt < 4; nt++)
#pragma unroll
            for (int j = 0; j < 4; j++) acc[mt][nt][j] = 0.f;

    int pix0 = blockIdx.x * 128;
    int arow = tid >> 1, acol = (tid & 1) * 32;

    for (int chunk = 0; chunk < 13; chunk++) {
        __syncthreads();
        {
            const uint4* asrc = (const uint4*)(g_xb + (size_t)(pix0 + arow) * 832 + chunk * 64 + acol);
            uint4* adst = (uint4*)(As + arow * 72 + acol);
            adst[0] = asrc[0]; adst[1] = asrc[1]; adst[2] = asrc[2]; adst[3] = asrc[3];
        }
#pragma unroll
        for (int i = 0; i < 2; i++) {
            int idx = tid + i * 256;
            int row = idx >> 3, seg = idx & 7;
            *(uint4*)(Bs + row * 72 + seg * 8) =
                *(const uint4*)(g_w1k + chunk * 4096 + row * 64 + seg * 8);
        }
        __syncthreads();
#pragma unroll
        for (int ks = 0; ks < 4; ks++) {
            int k0 = ks * 16;
            uint32_t a[2][4], bb[4][2];
#pragma unroll
            for (int mt = 0; mt < 2; mt++) {
                int row0 = wm * 32 + mt * 16 + g;
                a[mt][0] = *(const uint32_t*)(As + row0 * 72 + k0 + 2 * t);
                a[mt][1] = *(const uint32_t*)(As + (row0 + 8) * 72 + k0 + 2 * t);
                a[mt][2] = *(const uint32_t*)(As + row0 * 72 + k0 + 2 * t + 8);
                a[mt][3] = *(const uint32_t*)(As + (row0 + 8) * 72 + k0 + 2 * t + 8);
            }
#pragma unroll
            for (int nt = 0; nt < 4; nt++) {
                int n = wn * 32 + nt * 8 + g;
                bb[nt][0] = *(const uint32_t*)(Bs + n * 72 + k0 + 2 * t);
                bb[nt][1] = *(const uint32_t*)(Bs + n * 72 + k0 + 2 * t + 8);
            }
#pragma unroll
            for (int mt = 0; mt < 2; mt++)
#pragma unroll
                for (int nt = 0; nt < 4; nt++)
                    mma16816(acc[mt][nt], a[mt], bb[nt]);
        }
    }
#pragma unroll
    for (int mt = 0; mt < 2; mt++) {
        int row = wm * 32 + mt * 16 + g;
#pragma unroll
        for (int nt = 0; nt < 4; nt++) {
            int col = wn * 32 + nt * 8 + 2 * t;
            float* dst = g_h + (size_t)(pix0 + row) * 64 + col;
            *(float2*)dst = make_float2(acc[mt][nt][0], acc[mt][nt][1]);
            *(float2*)(dst + 512) = make_float2(acc[mt][nt][2], acc[mt][nt][3]);
        }
    }
}

// ---------------- 3x3 conv via mma.sync implicit GEMM ----------------
// CTA: 16x8 pixel tile x 64 oc. Halo 18x10x64 + 9 weight tiles in dyn smem.
#define CONV_SMEM (180 * 72 * 2 + 9 * 64 * 72 * 2)
__global__ void __launch_bounds__(256) k_conv_mma(int which) {
    extern __shared__ __nv_bfloat16 sm[];
    __nv_bfloat16* halo = sm;                 // [pix 180][72]
    __nv_bfloat16* Bs = sm + 180 * 72;        // [tap 9][64][72]
    int tid = threadIdx.x;
    int warp = tid >> 5, lane = tid & 31;
    int g = lane >> 2, t = lane & 3;
    int wm = warp & 3, wn = warp >> 2;
    int b = blockIdx.x >> 7;
    int tile = blockIdx.x & 127;
    int y0 = (tile >> 4) * 16, x0 = (tile & 15) * 8;

    for (int idx = tid; idx < 1440; idx += 256) {
        int pix = idx >> 3, seg = idx & 7;
        int yy = pix / 10, xx = pix - yy * 10;
        int gy = y0 + yy - 1, gx = x0 + xx - 1;
        uint4 v = make_uint4(0, 0, 0, 0);
        if (gy >= 0 && gy < 128 && gx >= 0 && gx < 128)
            v = *(const uint4*)(g_ab + (size_t)((b << 14) + (gy << 7) + gx) * 64 + seg * 8);
        *(uint4*)(halo + pix * 72 + seg * 8) = v;
    }
    for (int idx = tid; idx < 4608; idx += 256) {
        int tap = idx >> 9, rem = idx & 511;
        int row = rem >> 3, seg = rem & 7;
        *(uint4*)(Bs + tap * 4608 + row * 72 + seg * 8) =
            *(const uint4*)(g_wck[which] + tap * 4096 + row * 64 + seg * 8);
    }
    __syncthreads();

    float acc[2][4][4];
#pragma unroll
    for (int mt = 0; mt < 2; mt++)
#pragma unroll
        for (int nt = 0; nt < 4; nt++)
#pragma unroll
            for (int j = 0; j < 4; j++) acc[mt][nt][j] = 0.f;

#pragma unroll 1
    for (int tap = 0; tap < 9; tap++) {
        int dy = tap / 3 - 1, dx = tap % 3 - 1;
        const __nv_bfloat16* Bt = Bs + tap * 4608;
#pragma unroll
        for (int ks = 0; ks < 4; ks++) {
            int k0 = ks * 16;
            uint32_t a[2][4], bb[4][2];
#pragma unroll
            for (int mt = 0; mt < 2; mt++) {
                int ry = wm * 4 + mt * 2;
                int p0 = (ry + 1 + dy) * 10 + (g + 1 + dx);
                int p1 = p0 + 10;
                a[mt][0] = *(const uint32_t*)(halo + p0 * 72 + k0 + 2 * t);
                a[mt][1] = *(const uint32_t*)(halo + p1 * 72 + k0 + 2 * t);
                a[mt][2] = *(const uint32_t*)(halo + p0 * 72 + k0 + 2 * t + 8);
                a[mt][3] = *(const uint32_t*)(halo + p1 * 72 + k0 + 2 * t + 8);
            }
#pragma unroll
            for (int nt = 0; nt < 4; nt++) {
                int n = wn * 32 + nt * 8 + g;
                bb[nt][0] = *(const uint32_t*)(Bt + n * 72 + k0 + 2 * t);
                bb[nt][1] = *(const uint32_t*)(Bt + n * 72 + k0 + 2 * t + 8);
            }
#pragma unroll
            for (int mt = 0; mt < 2; mt++)
#pragma unroll
                for (int nt = 0; nt < 4; nt++)
                    mma16816(acc[mt][nt], a[mt], bb[nt]);
        }
    }
#pragma unroll
    for (int mt = 0; mt < 2; mt++) {
        int row = wm * 32 + mt * 16 + g;
        int py = y0 + (row >> 3), px = x0 + (row & 7);
#pragma unroll
        for (int nt = 0; nt < 4; nt++) {
            int col = wn * 32 + nt * 8 + 2 * t;
            float* dst = g_h + (size_t)((b << 14) + (py << 7) + px) * 64 + col;
            *(float2*)dst = make_float2(acc[mt][nt][0], acc[mt][nt][1]);
            float* dst2 = g_h + (size_t)((b << 14) + ((py + 1) << 7) + px) * 64 + col;
            *(float2*)dst2 = make_float2(acc[mt][nt][2], acc[mt][nt][3]);
        }
    }
}

// ---------------- GN stats stage 1 ----------------
__global__ void k_stats1() {
    int blk = blockIdx.x;
    int b = blk >> 4, slice = blk & 15;
    const float4* base = (const float4*)(g_h + (size_t)(b * HWSZ + slice * 1024) * 64);
    int t = threadIdx.x;
    int chgrp = t & 15, prow = t >> 4;
    float4 s = {0, 0, 0, 0}, s2 = {0, 0, 0, 0};
    for (int k = 0; k < 64; k++) {
        float4 v = base[(prow + k * 16) * 16 + chgrp];
        s.x += v.x; s.y += v.y; s.z += v.z; s.w += v.w;
        s2.x += v.x * v.x; s2.y += v.y * v.y; s2.z += v.z * v.z; s2.w += v.w * v.w;
    }
    __shared__ float4 ss[256], ss2[256];
    int idx = chgrp * 16 + prow;
    ss[idx] = s; ss2[idx] = s2;
    __syncthreads();
    for (int o = 8; o; o >>= 1) {
        if (prow < o) {
            float4 a = ss[idx], bb = ss[idx + o];
            a.x += bb.x; a.y += bb.y; a.z += bb.z; a.w += bb.w;
            ss[idx] = a;
            float4 c = ss2[idx], d = ss2[idx + o];
            c.x += d.x; c.y += d.y; c.z += d.z; c.w += d.w;
            ss2[idx] = c;
        }
        __syncthreads();
    }
    if (prow == 0) {
        ((float4*)g_pcs)[(b * 16 + slice) * 16 + chgrp] = ss[idx];
        ((float4*)g_pcs2)[(b * 16 + slice) * 16 + chgrp] = ss2[idx];
    }
}

// ---------------- GN stats stage 2 ----------------
__global__ void k_stats2(const float* __restrict__ gam, const float* __restrict__ bet) {
    int t = threadIdx.x;
    int b = t >> 6, c = t & 63;
    float s = 0.f, s2 = 0.f;
    for (int sl = 0; sl < 16; sl++) {
        s += g_pcs[(b * 16 + sl) * 64 + c];
        s2 += g_pcs2[(b * 16 + sl) * 64 + c];
    }
    __shared__ float cs[128], cs2[128];
    cs[t] = s; cs2[t] = s2;
    __syncthreads();
    float gs = 0.f, gs2 = 0.f;
    int gb = t & ~7;
#pragma unroll
    for (int j = 0; j < 8; j++) { gs += cs[gb + j]; gs2 += cs2[gb + j]; }
    float mu = gs * (1.f / 131072.f);
    float var = gs2 * (1.f / 131072.f) - mu * mu;
    float sc = gam[c] * rsqrtf(var + 1e-5f);
    g_gns[t] = sc;
    g_gnt[t] = bet[c] - mu * sc;
}

// ---------------- act: g_ab = bf16(gelu(g_h * s + t)) ----------------
__global__ void k_act() {
    int i = blockIdx.x * blockDim.x + threadIdx.x;
    float4 v = ((const float4*)g_h)[i];
    int c = (i & 15) * 4;
    int b = i >> 18;
    int bc = b * 64 + c;
    v.x = geluf(fmaf(v.x, g_gns[bc], g_gnt[bc]));
    v.y = geluf(fmaf(v.y, g_gns[bc + 1], g_gnt[bc + 1]));
    v.z = geluf(fmaf(v.z, g_gns[bc + 2], g_gnt[bc + 2]));
    v.w = geluf(fmaf(v.w, g_gns[bc + 3], g_gnt[bc + 3]));
    uint2 o;
    ((__nv_bfloat162*)&o)[0] = __floats2bfloat162_rn(v.x, v.y);
    ((__nv_bfloat162*)&o)[1] = __floats2bfloat162_rn(v.z, v.w);
    ((uint2*)g_ab)[i] = o;
}

// ---------------- heads ----------------
__global__ void __launch_bounds__(256) k_heads(const float* __restrict__ dw, const float* __restrict__ db,
                                               const float* __restrict__ cwt, const float* __restrict__ cb,
                                               const float* __restrict__ warp, const float* __restrict__ conf,
                                               float* __restrict__ out) {
    __shared__ float sw[3 * 9 * 64];
    int tid = threadIdx.x;
    for (int idx = tid; idx < 1728; idx += 256) {
        int o = idx / 576, rem = idx - o * 576;
        int tap = rem >> 6, c = rem & 63;
        sw[idx] = (o < 2) ? dw[(o * 64 + c) * 9 + tap] : cwt[c * 9 + tap];
    }
    __syncthreads();
    int wr = tid >> 5, lane = tid & 31;
    int p0 = (blockIdx.x * 8 + wr) * 4;
    int b = p0 >> 14, hw = p0 & 16383;
    int y = hw >> 7, x0 = hw & 127;
    int c2 = lane * 2;

    float nb[3][6][2];
#pragma unroll
    for (int ry = 0; ry < 3; ry++) {
        int yy = y - 1 + ry;
#pragma unroll
        for (int cx = 0; cx < 6; cx++) {
            int xx = x0 - 1 + cx;
            float v0 = 0.f, v1 = 0.f;
            if (yy >= 0 && yy < 128 && xx >= 0 && xx < 128) {
                __nv_bfloat162 h = *(const __nv_bfloat162*)(g_ab + (size_t)((b << 14) + (yy << 7) + xx) * 64 + c2);
                float2 f = __bfloat1622float2(h);
                v0 = f.x; v1 = f.y;
            }
            nb[ry][cx][0] = v0; nb[ry][cx][1] = v1;
        }
    }
    float acc[4][3];
#pragma unroll
    for (int j = 0; j < 4; j++)
#pragma unroll
        for (int o = 0; o < 3; o++) acc[j][o] = 0.f;
#pragma unroll
    for (int ky = 0; ky < 3; ky++)
#pragma unroll
        for (int kx = 0; kx < 3; kx++) {
            int tap = ky * 3 + kx;
            float w0a = sw[tap * 64 + c2], w0b = sw[tap * 64 + c2 + 1];
            float w1a = sw[576 + tap * 64 + c2], w1b = sw[576 + tap * 64 + c2 + 1];
            float w2a = sw[1152 + tap * 64 + c2], w2b = sw[1152 + tap * 64 + c2 + 1];
#pragma unroll
            for (int j = 0; j < 4; j++) {
                float v0 = nb[ky][j + kx][0], v1 = nb[ky][j + kx][1];
                acc[j][0] += w0a * v0 + w0b * v1;
                acc[j][1] += w1a * v0 + w1b * v1;
                acc[j][2] += w2a * v0 + w2b * v1;
            }
        }
#pragma unroll
    for (int o = 16; o; o >>= 1)
#pragma unroll
        for (int j = 0; j < 4; j++) {
            acc[j][0] += __shfl_xor_sync(0xffffffffu, acc[j][0], o);
            acc[j][1] += __shfl_xor_sync(0xffffffffu, acc[j][1], o);
            acc[j][2] += __shfl_xor_sync(0xffffffffu, acc[j][2], o);
        }
    if (lane < 4) {
        int p = p0 + lane;
        float a0 = acc[lane][0], a1 = acc[lane][1], a2 = acc[lane][2];
        float rx = clean15(warp[2 * p]);
        float ry = clean15(warp[2 * p + 1]);
        float fwx = fminf(fmaxf(rx + tanhf(a0 + db[0]) * 0.0625f, -1.5f), 1.5f);
        float fwy = fminf(fmaxf(ry + tanhf(a1 + db[1]) * 0.0625f, -1.5f), 1.5f);
        float cv = conf[p];
        if (!(cv == cv)) cv = 0.f;
        cv = fminf(fmaxf(cv, 0.f), 1.f);
        float pp = fminf(fmaxf(cv, 1e-4f), 1.f - 1e-4f);
        float base = logf(pp) - log1pf(-pp);
        float lg = base + 0.5f * (a2 + cb[0]);
        float rc = fminf(fmaxf(1.f / (1.f + expf(-lg)), 0.f), 1.f);
        out[2 * p] = fwx;
        out[2 * p + 1] = fwy;
        out[65536 + p] = rc;
        out[98304 + p] = lg;
    }
}

extern "C" void kernel_launch(void* const* d_in, const int* in_sizes, int n_in,
                              void* d_out, int out_size) {
    (void)in_sizes; (void)n_in; (void)out_size;
    const float* fA  = (const float*)d_in[0];
    const float* fB  = (const float*)d_in[1];
    const float* cw  = (const float*)d_in[2];
    const float* cf  = (const float*)d_in[3];
    const float* e1w = (const float*)d_in[4];
    const float* g1g = (const float*)d_in[5];
    const float* g1b = (const float*)d_in[6];
    const float* e2w = (const float*)d_in[7];
    const float* g2g = (const float*)d_in[8];
    const float* g2b = (const float*)d_in[9];
    const float* e3w = (const float*)d_in[10];
    const float* g3g = (const float*)d_in[11];
    const float* g3b = (const float*)d_in[12];
    const float* dw  = (const float*)d_in[13];
    const float* db  = (const float*)d_in[14];
    const float* cwt = (const float*)d_in[15];
    const float* cb  = (const float*)d_in[16];
    float* out = (float*)d_out;

    cudaFuncSetAttribute(k_conv_mma, cudaFuncAttributeMaxDynamicSharedMemorySize, CONV_SMEM);

    k_transpose<<<dim3(512, 8, 4), dim3(32, 8)>>>(fA, fB);
    k_w1k<<<208, 256>>>(e1w);
    k_wck<<<144, 256>>>(e2w, 0);
    k_wck<<<144, 256>>>(e3w, 1);
    k_features<<<4096, 256>>>(cw, cf);
    k_gemm1_mma<<<256, 256>>>();
    k_stats1<<<32, 256>>>();
    k_stats2<<<1, 128>>>(g1g, g1b);
    k_act<<<2048, 256>>>();
    k_conv_mma<<<256, 256, CONV_SMEM>>>(0);
    k_stats1<<<32, 256>>>();
    k_stats2<<<1, 128>>>(g2g, g2b);
    k_act<<<2048, 256>>>();
    k_conv_mma<<<256, 256, CONV_SMEM>>>(1);
    k_stats1<<<32, 256>>>();
    k_stats2<<<1, 128>>>(g3g, g3b);
    k_act<<<2048, 256>>>();
    k_heads<<<1024, 256>>>(dw, db, cwt, cb, cw, cf, out);
}

// round 6
// speedup vs baseline: 2.7715x; 1.1048x over previous
#include <cuda_runtime.h>
#include <cuda_bf16.h>
#include <math.h>
#include <stdint.h>

#define HWSZ 16384
#define NPIX 32768
#define CC 256

// ---------------- static device scratch ----------------
__device__ __align__(16) __nv_bfloat16 g_faT[2 * HWSZ * CC];     // feat_A NHWC bf16
__device__ __align__(16) __nv_bfloat16 g_fbT[2 * HWSZ * CC];     // feat_B NHWC bf16
__device__ __align__(16) __nv_bfloat16 g_xb[(size_t)NPIX * 832]; // X features bf16 (780 pad->832)
__device__ __align__(16) __nv_bfloat16 g_w1k[13 * 4096];         // enc1 W [chunk][oc][k64]
__device__ __align__(16) __nv_bfloat16 g_wck[2][9 * 4096];       // conv W [tap][oc][ci]
__device__ __align__(16) float g_h1[(size_t)NPIX * 64];          // raw layer out ping
__device__ __align__(16) float g_h2[(size_t)NPIX * 64];          // raw layer out pong
__device__ float g_gns[128];
__device__ float g_gnt[128];
__device__ float g_pcs[256 * 64];
__device__ float g_pcs2[256 * 64];

__device__ __forceinline__ float clean15(float v) {
    if (!(v == v)) return 0.f;
    return fminf(fmaxf(v, -1.5f), 1.5f);
}
__device__ __forceinline__ float geluf(float z) {
    return 0.5f * z * (1.f + erff(z * 0.70710678118654752f));
}

// bf16 HMMA: D(16x8,f32) += A(16x16,bf16) * B(8x16,bf16)^T
__device__ __forceinline__ void mma16816(float* d, const uint32_t* a, const uint32_t* b) {
    asm volatile(
        "mma.sync.aligned.m16n8k16.row.col.f32.bf16.bf16.f32 "
        "{%0,%1,%2,%3}, {%4,%5,%6,%7}, {%8,%9}, {%0,%1,%2,%3};"
        : "+f"(d[0]), "+f"(d[1]), "+f"(d[2]), "+f"(d[3])
        : "r"(a[0]), "r"(a[1]), "r"(a[2]), "r"(a[3]), "r"(b[0]), "r"(b[1]));
}

// ---------------- K0: NCHW fp32 -> NHWC bf16 transpose (bf16x2 stores) ----------------
__global__ void k_transpose(const float* __restrict__ fA, const float* __restrict__ fB) {
    __shared__ float tile[64][33];
    int z = blockIdx.z;
    const float* src = (z >= 2) ? fB : fA;
    __nv_bfloat16* dst = (z >= 2) ? g_fbT : g_faT;
    int b = z & 1;
    src += (size_t)b * CC * HWSZ;
    dst += (size_t)b * HWSZ * CC;
    int hw0 = blockIdx.x * 32, c0 = blockIdx.y * 64;
    int tx = threadIdx.x, ty = threadIdx.y;          // (32,8)
#pragma unroll
    for (int i = 0; i < 8; i++) {
        int cr = ty + i * 8;
        tile[cr][tx] = src[(c0 + cr) * HWSZ + hw0 + tx];
    }
    __syncthreads();
#pragma unroll
    for (int i = 0; i < 4; i++) {
        int r = ty + i * 8;
        __nv_bfloat162 v = __floats2bfloat162_rn(tile[2 * tx][r], tile[2 * tx + 1][r]);
        *(__nv_bfloat162*)(dst + (size_t)(hw0 + r) * CC + c0 + 2 * tx) = v;
    }
}

// ---------------- weight prep: all three in one launch ----------------
__global__ void k_wprep(const float* __restrict__ w1, const float* __restrict__ w2,
                        const float* __restrict__ w3) {
    int blk = blockIdx.x;
    if (blk < 208) {
        int idx = blk * 256 + threadIdx.x;
        if (idx >= 13 * 4096) return;
        int chunk = idx >> 12, rem = idx & 4095;
        int oc = rem >> 6, k = rem & 63;
        int kg = chunk * 64 + k;
        g_w1k[idx] = __float2bfloat16((kg < 780) ? w1[oc * 780 + kg] : 0.f);
    } else {
        int which = (blk < 352) ? 0 : 1;
        const float* w = which ? w3 : w2;
        int idx = (blk - (which ? 352 : 208)) * 256 + threadIdx.x;
        if (idx >= 9 * 4096) return;
        int tap = idx >> 12, rem = idx & 4095;
        int oc = rem >> 6, ci = rem & 63;
        g_wck[which][idx] = __float2bfloat16(w[(oc * 64 + ci) * 9 + tap]);
    }
}

// ---------------- K1: per-pixel features (warp per pixel) ----------------
__global__ void __launch_bounds__(256) k_features(const float* __restrict__ cw,
                                                  const float* __restrict__ cf) {
    int p = blockIdx.x * 8 + (threadIdx.x >> 5);
    int lane = threadIdx.x & 31;
    int b = p >> 14, hw = p & 16383;
    int py = hw >> 7, px = hw & 127;

    float gx = clean15(cw[2 * p]);
    float gy = clean15(cw[2 * p + 1]);
    float xc = fmaf(gx, 64.f, 63.5f);
    float yc = fmaf(gy, 64.f, 63.5f);
    float x0f = floorf(xc), y0f = floorf(yc);
    float wx = xc - x0f, wy = yc - y0f;
    float iwx = 1.f - wx, iwy = 1.f - wy;
    int x0 = (int)x0f, y0 = (int)y0f;

    int off[4][4];
#pragma unroll
    for (int t = 0; t < 4; t++) {
        int cyp = min(max(y0 - 1 + t, 0), 127);
#pragma unroll
        for (int u = 0; u < 4; u++) {
            int cxp = min(max(x0 - 1 + u, 0), 127);
            off[t][u] = (((b << 14) + (cyp << 7) + cxp) << 8);
        }
    }

    const __nv_bfloat16* fap = g_faT + ((size_t)((b << 14) | hw) << 8);
    __nv_bfloat16* xrow = g_xb + (size_t)p * 832;
    int c = lane * 8;

    uint4 faU = *(const uint4*)(fap + c);
    float fav[8];
    {
        const __nv_bfloat162* h = (const __nv_bfloat162*)&faU;
#pragma unroll
        for (int j = 0; j < 4; j++) {
            float2 f = __bfloat1622float2(h[j]);
            fav[2 * j] = f.x; fav[2 * j + 1] = f.y;
        }
    }
    float na = 0.f, ns[9], dt[9];
#pragma unroll
    for (int s = 0; s < 9; s++) { ns[s] = 0.f; dt[s] = 0.f; }
#pragma unroll
    for (int j = 0; j < 8; j++) na += fav[j] * fav[j];
    *(uint4*)(xrow + c) = faU;

    float lxp[3][8];
    float wv[8];
#pragma unroll
    for (int t = 0; t < 4; t++) {
        float cv[4][8];
#pragma unroll
        for (int u = 0; u < 4; u++) {
            uint4 U = *(const uint4*)(g_fbT + off[t][u] + c);
            const __nv_bfloat162* h = (const __nv_bfloat162*)&U;
#pragma unroll
            for (int j = 0; j < 4; j++) {
                float2 f = __bfloat1622float2(h[j]);
                cv[u][2 * j] = f.x; cv[u][2 * j + 1] = f.y;
            }
        }
        float lx[3][8];
#pragma unroll
        for (int j = 0; j < 8; j++) {
            lx[0][j] = cv[0][j] * iwx + cv[1][j] * wx;
            lx[1][j] = cv[1][j] * iwx + cv[2][j] * wx;
            lx[2][j] = cv[2][j] * iwx + cv[3][j] * wx;
        }
        if (t > 0) {
            int dyrow = t - 1;
#pragma unroll
            for (int i = 0; i < 3; i++) {
                int s = dyrow * 3 + i;
#pragma unroll
                for (int j = 0; j < 8; j++) {
                    float v = lxp[i][j] * iwy + lx[i][j] * wy;
                    ns[s] += v * v;
                    dt[s] += fav[j] * v;
                    if (dyrow == 1 && i == 1) wv[j] = v;
                }
            }
        }
#pragma unroll
        for (int i = 0; i < 3; i++)
#pragma unroll
            for (int j = 0; j < 8; j++) lxp[i][j] = lx[i][j];
    }
    {
        uint4 W, D;
        __nv_bfloat162* wh = (__nv_bfloat162*)&W;
        __nv_bfloat162* dh = (__nv_bfloat162*)&D;
#pragma unroll
        for (int j = 0; j < 4; j++) {
            wh[j] = __floats2bfloat162_rn(wv[2 * j], wv[2 * j + 1]);
            dh[j] = __floats2bfloat162_rn(fabsf(fav[2 * j] - wv[2 * j]),
                                          fabsf(fav[2 * j + 1] - wv[2 * j + 1]));
        }
        *(uint4*)(xrow + 256 + c) = W;
        *(uint4*)(xrow + 512 + c) = D;
    }

#pragma unroll
    for (int o = 16; o; o >>= 1) {
        na += __shfl_xor_sync(0xffffffffu, na, o);
#pragma unroll
        for (int s = 0; s < 9; s++) {
            ns[s] += __shfl_xor_sync(0xffffffffu, ns[s], o);
            dt[s] += __shfl_xor_sync(0xffffffffu, dt[s], o);
        }
    }
    if (lane == 0) {
        float sna = fmaxf(sqrtf(na), 1e-12f);
        float dispx = gx - ((px + 0.5f) * (2.f / 128.f) - 1.f);
        float dispy = gy - ((py + 0.5f) * (2.f / 128.f) - 1.f);
        float cfv = cf[p];
        if (!(cfv == cfv)) cfv = 0.f;
        cfv = fminf(fmaxf(cfv, 0.f), 1.f);
        xrow[768] = __float2bfloat16(dispx);
        xrow[769] = __float2bfloat16(dispy);
        xrow[770] = __float2bfloat16(cfv);
#pragma unroll
        for (int s = 0; s < 9; s++)
            xrow[771 + s] = __float2bfloat16(dt[s] / (sna * fmaxf(sqrtf(ns[s]), 1e-12f)));
    } else if (lane <= 13) {
        ((uint2*)(xrow + 780))[lane - 1] = make_uint2(0u, 0u);   // zero pad 780..831
    }
}

// ---------------- shared epilogue: per-CTA (sum, sumsq) per channel ----------------
// acc layout: acc[mt][nt][j]; cols = wn*32 + nt*8 + 2t (+1 for odd j)
#define STATS_EPILOGUE(ACC, SRED, SRED2, SLOT)                                        \
    {                                                                                 \
        float ps[4][2], pq[4][2];                                                     \
        _Pragma("unroll")                                                             \
        for (int nt = 0; nt < 4; nt++) {                                              \
            float v0 = ACC[0][nt][0], v1 = ACC[0][nt][2],                             \
                  v2 = ACC[1][nt][0], v3 = ACC[1][nt][2];                             \
            ps[nt][0] = v0 + v1 + v2 + v3;                                            \
            pq[nt][0] = v0 * v0 + v1 * v1 + v2 * v2 + v3 * v3;                        \
            float u0 = ACC[0][nt][1], u1 = ACC[0][nt][3],                             \
                  u2 = ACC[1][nt][1], u3 = ACC[1][nt][3];                             \
            ps[nt][1] = u0 + u1 + u2 + u3;                                            \
            pq[nt][1] = u0 * u0 + u1 * u1 + u2 * u2 + u3 * u3;                        \
        }                                                                             \
        _Pragma("unroll")                                                             \
        for (int o = 4; o <= 16; o <<= 1)                                             \
            _Pragma("unroll")                                                         \
            for (int nt = 0; nt < 4; nt++)                                            \
                _Pragma("unroll")                                                     \
                for (int pr = 0; pr < 2; pr++) {                                      \
                    ps[nt][pr] += __shfl_xor_sync(0xffffffffu, ps[nt][pr], o);        \
                    pq[nt][pr] += __shfl_xor_sync(0xffffffffu, pq[nt][pr], o);        \
                }                                                                     \
        if (lane < 4) {                                                               \
            _Pragma("unroll")                                                         \
            for (int nt = 0; nt < 4; nt++)                                            \
                _Pragma("unroll")                                                     \
                for (int pr = 0; pr < 2; pr++) {                                      \
                    SRED[warp][nt * 8 + 2 * lane + pr] = ps[nt][pr];                  \
                    SRED2[warp][nt * 8 + 2 * lane + pr] = pq[nt][pr];                 \
                }                                                                     \
        }                                                                             \
        __syncthreads();                                                              \
        if (tid < 64) {                                                               \
            int wn2 = tid >> 5, j2 = tid & 31;                                        \
            float ssum = 0.f, qsum = 0.f;                                             \
            _Pragma("unroll")                                                         \
            for (int wm2 = 0; wm2 < 4; wm2++) {                                       \
                ssum += SRED[wn2 * 4 + wm2][j2];                                      \
                qsum += SRED2[wn2 * 4 + wm2][j2];                                     \
            }                                                                         \
            g_pcs[(size_t)(SLOT) * 64 + wn2 * 32 + j2] = ssum;                        \
            g_pcs2[(size_t)(SLOT) * 64 + wn2 * 32 + j2] = qsum;                       \
        }                                                                             \
    }

// ---------------- enc1 GEMM via mma.sync + stats epilogue ----------------
__global__ void __launch_bounds__(256) k_gemm1_mma() {
    __shared__ __align__(16) __nv_bfloat16 As[128 * 72];
    __shared__ __align__(16) __nv_bfloat16 Bs[64 * 72];
    __shared__ float sred[8][32], sred2[8][32];
    int tid = threadIdx.x;
    int warp = tid >> 5, lane = tid & 31;
    int g = lane >> 2, t = lane & 3;
    int wm = warp & 3, wn = warp >> 2;
    float acc[2][4][4];
#pragma unroll
    for (int mt = 0; mt < 2; mt++)
#pragma unroll
        for (int nt = 0; nt < 4; nt++)
#pragma unroll
            for (int j = 0; j < 4; j++) acc[mt][nt][j] = 0.f;

    int pix0 = blockIdx.x * 128;
    int arow = tid >> 1, acol = (tid & 1) * 32;

    for (int chunk = 0; chunk < 13; chunk++) {
        __syncthreads();
        {
            const uint4* asrc = (const uint4*)(g_xb + (size_t)(pix0 + arow) * 832 + chunk * 64 + acol);
            uint4* adst = (uint4*)(As + arow * 72 + acol);
            adst[0] = asrc[0]; adst[1] = asrc[1]; adst[2] = asrc[2]; adst[3] = asrc[3];
        }
#pragma unroll
        for (int i = 0; i < 2; i++) {
            int idx = tid + i * 256;
            int row = idx >> 3, seg = idx & 7;
            *(uint4*)(Bs + row * 72 + seg * 8) =
                *(const uint4*)(g_w1k + chunk * 4096 + row * 64 + seg * 8);
        }
        __syncthreads();
#pragma unroll
        for (int ks = 0; ks < 4; ks++) {
            int k0 = ks * 16;
            uint32_t a[2][4], bb[4][2];
#pragma unroll
            for (int mt = 0; mt < 2; mt++) {
                int row0 = wm * 32 + mt * 16 + g;
                a[mt][0] = *(const uint32_t*)(As + row0 * 72 + k0 + 2 * t);
                a[mt][1] = *(const uint32_t*)(As + (row0 + 8) * 72 + k0 + 2 * t);
                a[mt][2] = *(const uint32_t*)(As + row0 * 72 + k0 + 2 * t + 8);
                a[mt][3] = *(const uint32_t*)(As + (row0 + 8) * 72 + k0 + 2 * t + 8);
            }
#pragma unroll
            for (int nt = 0; nt < 4; nt++) {
                int n = wn * 32 + nt * 8 + g;
                bb[nt][0] = *(const uint32_t*)(Bs + n * 72 + k0 + 2 * t);
                bb[nt][1] = *(const uint32_t*)(Bs + n * 72 + k0 + 2 * t + 8);
            }
#pragma unroll
            for (int mt = 0; mt < 2; mt++)
#pragma unroll
                for (int nt = 0; nt < 4; nt++)
                    mma16816(acc[mt][nt], a[mt], bb[nt]);
        }
    }
#pragma unroll
    for (int mt = 0; mt < 2; mt++) {
        int row = wm * 32 + mt * 16 + g;
#pragma unroll
        for (int nt = 0; nt < 4; nt++) {
            int col = wn * 32 + nt * 8 + 2 * t;
            float* dst = g_h1 + (size_t)(pix0 + row) * 64 + col;
            *(float2*)dst = make_float2(acc[mt][nt][0], acc[mt][nt][1]);
            *(float2*)(dst + 512) = make_float2(acc[mt][nt][2], acc[mt][nt][3]);
        }
    }
    __syncthreads();
    STATS_EPILOGUE(acc, sred, sred2, blockIdx.x)
}

// ---------------- 3x3 conv via mma.sync, GN+GELU fused input, stats epilogue ----------------
#define CONV_SMEM (180 * 72 * 2 + 9 * 64 * 72 * 2)
__global__ void __launch_bounds__(256) k_conv_mma(int which, int srcsel) {
    extern __shared__ __nv_bfloat16 sm[];
    __nv_bfloat16* halo = sm;                 // [pix 180][72]
    __nv_bfloat16* Bs = sm + 180 * 72;        // [tap 9][64][72]
    __shared__ float sg[64], st[64];
    __shared__ float sred[8][32], sred2[8][32];
    const float* src = srcsel ? g_h2 : g_h1;
    float* dst = srcsel ? g_h1 : g_h2;
    int tid = threadIdx.x;
    int warp = tid >> 5, lane = tid & 31;
    int g = lane >> 2, t = lane & 3;
    int wm = warp & 3, wn = warp >> 2;
    int b = blockIdx.x >> 7;
    int tile = blockIdx.x & 127;
    int y0 = (tile >> 4) * 16, x0 = (tile & 15) * 8;

    if (tid < 64) { sg[tid] = g_gns[b * 64 + tid]; st[tid] = g_gnt[b * 64 + tid]; }
    __syncthreads();

    for (int idx = tid; idx < 1440; idx += 256) {
        int pix = idx >> 3, seg = idx & 7;
        int yy = pix / 10, xx = pix - yy * 10;
        int gy = y0 + yy - 1, gx = x0 + xx - 1;
        uint4 v = make_uint4(0, 0, 0, 0);
        if (gy >= 0 && gy < 128 && gx >= 0 && gx < 128) {
            const float4* sp = (const float4*)(src + (size_t)((b << 14) + (gy << 7) + gx) * 64 + seg * 8);
            float4 r0 = sp[0], r1 = sp[1];
            int cb = seg * 8;
            float o0 = geluf(fmaf(r0.x, sg[cb], st[cb]));
            float o1 = geluf(fmaf(r0.y, sg[cb + 1], st[cb + 1]));
            float o2 = geluf(fmaf(r0.z, sg[cb + 2], st[cb + 2]));
            float o3 = geluf(fmaf(r0.w, sg[cb + 3], st[cb + 3]));
            float o4 = geluf(fmaf(r1.x, sg[cb + 4], st[cb + 4]));
            float o5 = geluf(fmaf(r1.y, sg[cb + 5], st[cb + 5]));
            float o6 = geluf(fmaf(r1.z, sg[cb + 6], st[cb + 6]));
            float o7 = geluf(fmaf(r1.w, sg[cb + 7], st[cb + 7]));
            __nv_bfloat162* vh = (__nv_bfloat162*)&v;
            vh[0] = __floats2bfloat162_rn(o0, o1);
            vh[1] = __floats2bfloat162_rn(o2, o3);
            vh[2] = __floats2bfloat162_rn(o4, o5);
            vh[3] = __floats2bfloat162_rn(o6, o7);
        }
        *(uint4*)(halo + pix * 72 + seg * 8) = v;
    }
    for (int idx = tid; idx < 4608; idx += 256) {
        int tap = idx >> 9, rem = idx & 511;
        int row = rem >> 3, seg = rem & 7;
        *(uint4*)(Bs + tap * 4608 + row * 72 + seg * 8) =
            *(const uint4*)(g_wck[which] + tap * 4096 + row * 64 + seg * 8);
    }
    __syncthreads();

    float acc[2][4][4];
#pragma unroll
    for (int mt = 0; mt < 2; mt++)
#pragma unroll
        for (int nt = 0; nt < 4; nt++)
#pragma unroll
            for (int j = 0; j < 4; j++) acc[mt][nt][j] = 0.f;

#pragma unroll 1
    for (int tap = 0; tap < 9; tap++) {
        int dy = tap / 3 - 1, dx = tap % 3 - 1;
        const __nv_bfloat16* Bt = Bs + tap * 4608;
#pragma unroll
        for (int ks = 0; ks < 4; ks++) {
            int k0 = ks * 16;
            uint32_t a[2][4], bb[4][2];
#pragma unroll
            for (int mt = 0; mt < 2; mt++) {
                int ry = wm * 4 + mt * 2;
                int p0 = (ry + 1 + dy) * 10 + (g + 1 + dx);
                int p1 = p0 + 10;
                a[mt][0] = *(const uint32_t*)(halo + p0 * 72 + k0 + 2 * t);
                a[mt][1] = *(const uint32_t*)(halo + p1 * 72 + k0 + 2 * t);
                a[mt][2] = *(const uint32_t*)(halo + p0 * 72 + k0 + 2 * t + 8);
                a[mt][3] = *(const uint32_t*)(halo + p1 * 72 + k0 + 2 * t + 8);
            }
#pragma unroll
            for (int nt = 0; nt < 4; nt++) {
                int n = wn * 32 + nt * 8 + g;
                bb[nt][0] = *(const uint32_t*)(Bt + n * 72 + k0 + 2 * t);
                bb[nt][1] = *(const uint32_t*)(Bt + n * 72 + k0 + 2 * t + 8);
            }
#pragma unroll
            for (int mt = 0; mt < 2; mt++)
#pragma unroll
                for (int nt = 0; nt < 4; nt++)
                    mma16816(acc[mt][nt], a[mt], bb[nt]);
        }
    }
#pragma unroll
    for (int mt = 0; mt < 2; mt++) {
        int row = wm * 32 + mt * 16 + g;
        int py = y0 + (row >> 3), px = x0 + (row & 7);
#pragma unroll
        for (int nt = 0; nt < 4; nt++) {
            int col = wn * 32 + nt * 8 + 2 * t;
            float* d1 = dst + (size_t)((b << 14) + (py << 7) + px) * 64 + col;
            *(float2*)d1 = make_float2(acc[mt][nt][0], acc[mt][nt][1]);
            float* d2 = dst + (size_t)((b << 14) + ((py + 1) << 7) + px) * 64 + col;
            *(float2*)d2 = make_float2(acc[mt][nt][2], acc[mt][nt][3]);
        }
    }
    __syncthreads();
    STATS_EPILOGUE(acc, sred, sred2, blockIdx.x)
}

// ---------------- GN stats stage 2: fold 128 CTA partials per batch ----------------
__global__ void k_stats2(const float* __restrict__ gam, const float* __restrict__ bet) {
    int tid = threadIdx.x;            // 256
    int half = tid >> 7;
    int t = tid & 127;
    int b = t >> 6, c = t & 63;
    float s = 0.f, s2 = 0.f;
    int base = b * 128 + half * 64;
#pragma unroll 4
    for (int sl = 0; sl < 64; sl++) {
        s += g_pcs[(size_t)(base + sl) * 64 + c];
        s2 += g_pcs2[(size_t)(base + sl) * 64 + c];
    }
    __shared__ float hs[2][128], hs2[2][128];
    __shared__ float cs[128], cs2[128];
    hs[half][t] = s; hs2[half][t] = s2;
    __syncthreads();
    if (half == 0) {
        cs[t] = hs[0][t] + hs[1][t];
        cs2[t] = hs2[0][t] + hs2[1][t];
    }
    __syncthreads();
    if (half == 0) {
        float gs = 0.f, gs2 = 0.f;
        int gb = t & ~7;
#pragma unroll
        for (int j = 0; j < 8; j++) { gs += cs[gb + j]; gs2 += cs2[gb + j]; }
        float mu = gs * (1.f / 131072.f);
        float var = gs2 * (1.f / 131072.f) - mu * mu;
        float sc = gam[c] * rsqrtf(var + 1e-5f);
        g_gns[t] = sc;
        g_gnt[t] = bet[c] - mu * sc;
    }
}

// ---------------- heads: GN+GELU fused, 3-out conv + epilogue ----------------
__global__ void __launch_bounds__(256) k_heads(const float* __restrict__ dw, const float* __restrict__ db,
                                               const float* __restrict__ cwt, const float* __restrict__ cb,
                                               const float* __restrict__ warp, const float* __restrict__ conf,
                                               float* __restrict__ out) {
    __shared__ float sw[3 * 9 * 64];
    int tid = threadIdx.x;
    for (int idx = tid; idx < 1728; idx += 256) {
        int o = idx / 576, rem = idx - o * 576;
        int tap = rem >> 6, c = rem & 63;
        sw[idx] = (o < 2) ? dw[(o * 64 + c) * 9 + tap] : cwt[c * 9 + tap];
    }
    __syncthreads();
    int wr = tid >> 5, lane = tid & 31;
    int p0 = (blockIdx.x * 8 + wr) * 4;
    int b = p0 >> 14, hw = p0 & 16383;
    int y = hw >> 7, x0 = hw & 127;
    int c2 = lane * 2;
    float s0 = g_gns[b * 64 + c2], s1 = g_gns[b * 64 + c2 + 1];
    float t0 = g_gnt[b * 64 + c2], t1 = g_gnt[b * 64 + c2 + 1];

    float nb[3][6][2];
#pragma unroll
    for (int ry = 0; ry < 3; ry++) {
        int yy = y - 1 + ry;
#pragma unroll
        for (int cx = 0; cx < 6; cx++) {
            int xx = x0 - 1 + cx;
            float v0 = 0.f, v1 = 0.f;
            if (yy >= 0 && yy < 128 && xx >= 0 && xx < 128) {
                float2 h = *(const float2*)(g_h1 + (size_t)((b << 14) + (yy << 7) + xx) * 64 + c2);
                v0 = geluf(fmaf(h.x, s0, t0));
                v1 = geluf(fmaf(h.y, s1, t1));
            }
            nb[ry][cx][0] = v0; nb[ry][cx][1] = v1;
        }
    }
    float acc[4][3];
#pragma unroll
    for (int j = 0; j < 4; j++)
#pragma unroll
        for (int o = 0; o < 3; o++) acc[j][o] = 0.f;
#pragma unroll
    for (int ky = 0; ky < 3; ky++)
#pragma unroll
        for (int kx = 0; kx < 3; kx++) {
            int tap = ky * 3 + kx;
            float w0a = sw[tap * 64 + c2], w0b = sw[tap * 64 + c2 + 1];
            float w1a = sw[576 + tap * 64 + c2], w1b = sw[576 + tap * 64 + c2 + 1];
            float w2a = sw[1152 + tap * 64 + c2], w2b = sw[1152 + tap * 64 + c2 + 1];
#pragma unroll
            for (int j = 0; j < 4; j++) {
                float v0 = nb[ky][j + kx][0], v1 = nb[ky][j + kx][1];
                acc[j][0] += w0a * v0 + w0b * v1;
                acc[j][1] += w1a * v0 + w1b * v1;
                acc[j][2] += w2a * v0 + w2b * v1;
            }
        }
#pragma unroll
    for (int o = 16; o; o >>= 1)
#pragma unroll
        for (int j = 0; j < 4; j++) {
            acc[j][0] += __shfl_xor_sync(0xffffffffu, acc[j][0], o);
            acc[j][1] += __shfl_xor_sync(0xffffffffu, acc[j][1], o);
            acc[j][2] += __shfl_xor_sync(0xffffffffu, acc[j][2], o);
        }
    if (lane < 4) {
        int p = p0 + lane;
        float a0 = acc[lane][0], a1 = acc[lane][1], a2 = acc[lane][2];
        float rx = clean15(warp[2 * p]);
        float ry = clean15(warp[2 * p + 1]);
        float fwx = fminf(fmaxf(rx + tanhf(a0 + db[0]) * 0.0625f, -1.5f), 1.5f);
        float fwy = fminf(fmaxf(ry + tanhf(a1 + db[1]) * 0.0625f, -1.5f), 1.5f);
        float cv = conf[p];
        if (!(cv == cv)) cv = 0.f;
        cv = fminf(fmaxf(cv, 0.f), 1.f);
        float pp = fminf(fmaxf(cv, 1e-4f), 1.f - 1e-4f);
        float base = logf(pp) - log1pf(-pp);
        float lg = base + 0.5f * (a2 + cb[0]);
        float rc = fminf(fmaxf(1.f / (1.f + expf(-lg)), 0.f), 1.f);
        out[2 * p] = fwx;
        out[2 * p + 1] = fwy;
        out[65536 + p] = rc;
        out[98304 + p] = lg;
    }
}

extern "C" void kernel_launch(void* const* d_in, const int* in_sizes, int n_in,
                              void* d_out, int out_size) {
    (void)in_sizes; (void)n_in; (void)out_size;
    const float* fA  = (const float*)d_in[0];
    const float* fB  = (const float*)d_in[1];
    const float* cw  = (const float*)d_in[2];
    const float* cf  = (const float*)d_in[3];
    const float* e1w = (const float*)d_in[4];
    const float* g1g = (const float*)d_in[5];
    const float* g1b = (const float*)d_in[6];
    const float* e2w = (const float*)d_in[7];
    const float* g2g = (const float*)d_in[8];
    const float* g2b = (const float*)d_in[9];
    const float* e3w = (const float*)d_in[10];
    const float* g3g = (const float*)d_in[11];
    const float* g3b = (const float*)d_in[12];
    const float* dw  = (const float*)d_in[13];
    const float* db  = (const float*)d_in[14];
    const float* cwt = (const float*)d_in[15];
    const float* cb  = (const float*)d_in[16];
    float* out = (float*)d_out;

    cudaFuncSetAttribute(k_conv_mma, cudaFuncAttributeMaxDynamicSharedMemorySize, CONV_SMEM);

    k_transpose<<<dim3(512, 4, 4), dim3(32, 8)>>>(fA, fB);
    k_wprep<<<496, 256>>>(e1w, e2w, e3w);
    k_features<<<4096, 256>>>(cw, cf);
    k_gemm1_mma<<<256, 256>>>();
    k_stats2<<<1, 256>>>(g1g, g1b);
    k_conv_mma<<<256, 256, CONV_SMEM>>>(0, 0);   // read g_h1 -> g_h2
    k_stats2<<<1, 256>>>(g2g, g2b);
    k_conv_mma<<<256, 256, CONV_SMEM>>>(1, 1);   // read g_h2 -> g_h1
    k_stats2<<<1, 256>>>(g3g, g3b);
    k_heads<<<1024, 256>>>(dw, db, cwt, cb, cw, cf, out);
}

// round 7
// speedup vs baseline: 2.8479x; 1.0276x over previous
#include <cuda_runtime.h>
#include <cuda_bf16.h>
#include <math.h>
#include <stdint.h>

#define HWSZ 16384
#define NPIX 32768
#define CC 256

// ---------------- static device scratch ----------------
__device__ __align__(16) __nv_bfloat16 g_fbT[2 * HWSZ * CC];     // feat_B NHWC bf16
__device__ __align__(16) __nv_bfloat16 g_xb[(size_t)NPIX * 832]; // X features bf16 (780 pad->832)
__device__ __align__(16) __nv_bfloat16 g_w1k[13 * 4096];         // enc1 W [chunk][oc][k64]
__device__ __align__(16) __nv_bfloat16 g_wck[2][9 * 4096];       // conv W [tap][oc][ci]
__device__ __align__(16) float g_h1[(size_t)NPIX * 64];          // raw layer out ping
__device__ __align__(16) float g_h2[(size_t)NPIX * 64];          // raw layer out pong
__device__ float g_gns[128];
__device__ float g_gnt[128];
__device__ float g_pcs[256 * 64];
__device__ float g_pcs2[256 * 64];

__device__ __forceinline__ float clean15(float v) {
    if (!(v == v)) return 0.f;
    return fminf(fmaxf(v, -1.5f), 1.5f);
}
__device__ __forceinline__ float geluf(float z) {
    return 0.5f * z * (1.f + erff(z * 0.70710678118654752f));
}
__device__ __forceinline__ uint32_t smem_u32(const void* p) {
    uint32_t r;
    asm("{ .reg .u64 t; cvta.to.shared.u64 t, %1; cvt.u32.u64 %0, t; }" : "=r"(r) : "l"(p));
    return r;
}
__device__ __forceinline__ void cp16(uint32_t dst, const void* src) {
    asm volatile("cp.async.cg.shared.global [%0], [%1], 16;" :: "r"(dst), "l"(src));
}
__device__ __forceinline__ void cp_commit() {
    asm volatile("cp.async.commit_group;" ::: "memory");
}
template <int N>
__device__ __forceinline__ void cp_wait() {
    asm volatile("cp.async.wait_group %0;" :: "n"(N) : "memory");
}

// bf16 HMMA: D(16x8,f32) += A(16x16,bf16) * B(8x16,bf16)^T
__device__ __forceinline__ void mma16816(float* d, const uint32_t* a, const uint32_t* b) {
    asm volatile(
        "mma.sync.aligned.m16n8k16.row.col.f32.bf16.bf16.f32 "
        "{%0,%1,%2,%3}, {%4,%5,%6,%7}, {%8,%9}, {%0,%1,%2,%3};"
        : "+f"(d[0]), "+f"(d[1]), "+f"(d[2]), "+f"(d[3])
        : "r"(a[0]), "r"(a[1]), "r"(a[2]), "r"(a[3]), "r"(b[0]), "r"(b[1]));
}

// ---------------- K0: NCHW fp32 -> bf16 transpose ----------------
// z=0,1: feat_A batches -> directly into g_xb rows (stride 832)
// z=2,3: feat_B batches -> g_fbT (stride 256)
__global__ void k_transpose(const float* __restrict__ fA, const float* __restrict__ fB) {
    __shared__ float tile[64][33];
    int z = blockIdx.z;
    const float* src = (z >= 2) ? fB : fA;
    int b = z & 1;
    src += (size_t)b * CC * HWSZ;
    __nv_bfloat16* dstbase;
    size_t stride;
    if (z < 2) { dstbase = g_xb + (size_t)(b << 14) * 832; stride = 832; }
    else       { dstbase = g_fbT + ((size_t)(b << 14) << 8); stride = 256; }
    int hw0 = blockIdx.x * 32, c0 = blockIdx.y * 64;
    int tx = threadIdx.x, ty = threadIdx.y;          // (32,8)
#pragma unroll
    for (int i = 0; i < 8; i++) {
        int cr = ty + i * 8;
        tile[cr][tx] = src[(c0 + cr) * HWSZ + hw0 + tx];
    }
    __syncthreads();
#pragma unroll
    for (int i = 0; i < 4; i++) {
        int r = ty + i * 8;
        __nv_bfloat162 v = __floats2bfloat162_rn(tile[2 * tx][r], tile[2 * tx + 1][r]);
        *(__nv_bfloat162*)(dstbase + (size_t)(hw0 + r) * stride + c0 + 2 * tx) = v;
    }
}

// ---------------- weight prep: all three in one launch ----------------
__global__ void k_wprep(const float* __restrict__ w1, const float* __restrict__ w2,
                        const float* __restrict__ w3) {
    int blk = blockIdx.x;
    if (blk < 208) {
        int idx = blk * 256 + threadIdx.x;
        if (idx >= 13 * 4096) return;
        int chunk = idx >> 12, rem = idx & 4095;
        int oc = rem >> 6, k = rem & 63;
        int kg = chunk * 64 + k;
        g_w1k[idx] = __float2bfloat16((kg < 780) ? w1[oc * 780 + kg] : 0.f);
    } else {
        int which = (blk < 352) ? 0 : 1;
        const float* w = which ? w3 : w2;
        int idx = (blk - (which ? 352 : 208)) * 256 + threadIdx.x;
        if (idx >= 9 * 4096) return;
        int tap = idx >> 12, rem = idx & 4095;
        int oc = rem >> 6, ci = rem & 63;
        g_wck[which][idx] = __float2bfloat16(w[(oc * 64 + ci) * 9 + tap]);
    }
}

// ---------------- K1: per-pixel features (warp per pixel) ----------------
__global__ void __launch_bounds__(256) k_features(const float* __restrict__ cw,
                                                  const float* __restrict__ cf) {
    int p = blockIdx.x * 8 + (threadIdx.x >> 5);
    int lane = threadIdx.x & 31;
    int b = p >> 14, hw = p & 16383;
    int py = hw >> 7, px = hw & 127;

    float gx = clean15(cw[2 * p]);
    float gy = clean15(cw[2 * p + 1]);
    float xc = fmaf(gx, 64.f, 63.5f);
    float yc = fmaf(gy, 64.f, 63.5f);
    float x0f = floorf(xc), y0f = floorf(yc);
    float wx = xc - x0f, wy = yc - y0f;
    float iwx = 1.f - wx, iwy = 1.f - wy;
    int x0 = (int)x0f, y0 = (int)y0f;

    int off[4][4];
#pragma unroll
    for (int t = 0; t < 4; t++) {
        int cyp = min(max(y0 - 1 + t, 0), 127);
#pragma unroll
        for (int u = 0; u < 4; u++) {
            int cxp = min(max(x0 - 1 + u, 0), 127);
            off[t][u] = (((b << 14) + (cyp << 7) + cxp) << 8);
        }
    }

    __nv_bfloat16* xrow = g_xb + (size_t)p * 832;
    int c = lane * 8;

    // feat_A channels already in xrow[0..255] (written by transpose)
    uint4 faU = *(const uint4*)(xrow + c);
    float fav[8];
    {
        const __nv_bfloat162* h = (const __nv_bfloat162*)&faU;
#pragma unroll
        for (int j = 0; j < 4; j++) {
            float2 f = __bfloat1622float2(h[j]);
            fav[2 * j] = f.x; fav[2 * j + 1] = f.y;
        }
    }
    float na = 0.f, ns[9], dt[9];
#pragma unroll
    for (int s = 0; s < 9; s++) { ns[s] = 0.f; dt[s] = 0.f; }
#pragma unroll
    for (int j = 0; j < 8; j++) na += fav[j] * fav[j];

    float lxp[3][8];
    float wv[8];
#pragma unroll
    for (int t = 0; t < 4; t++) {
        float cv[4][8];
#pragma unroll
        for (int u = 0; u < 4; u++) {
            uint4 U = *(const uint4*)(g_fbT + off[t][u] + c);
            const __nv_bfloat162* h = (const __nv_bfloat162*)&U;
#pragma unroll
            for (int j = 0; j < 4; j++) {
                float2 f = __bfloat1622float2(h[j]);
                cv[u][2 * j] = f.x; cv[u][2 * j + 1] = f.y;
            }
        }
        float lx[3][8];
#pragma unroll
        for (int j = 0; j < 8; j++) {
            lx[0][j] = cv[0][j] * iwx + cv[1][j] * wx;
            lx[1][j] = cv[1][j] * iwx + cv[2][j] * wx;
            lx[2][j] = cv[2][j] * iwx + cv[3][j] * wx;
        }
        if (t > 0) {
            int dyrow = t - 1;
#pragma unroll
            for (int i = 0; i < 3; i++) {
                int s = dyrow * 3 + i;
#pragma unroll
                for (int j = 0; j < 8; j++) {
                    float v = lxp[i][j] * iwy + lx[i][j] * wy;
                    ns[s] += v * v;
                    dt[s] += fav[j] * v;
                    if (dyrow == 1 && i == 1) wv[j] = v;
                }
            }
        }
#pragma unroll
        for (int i = 0; i < 3; i++)
#pragma unroll
            for (int j = 0; j < 8; j++) lxp[i][j] = lx[i][j];
    }
    {
        uint4 W, D;
        __nv_bfloat162* wh = (__nv_bfloat162*)&W;
        __nv_bfloat162* dh = (__nv_bfloat162*)&D;
#pragma unroll
        for (int j = 0; j < 4; j++) {
            wh[j] = __floats2bfloat162_rn(wv[2 * j], wv[2 * j + 1]);
            dh[j] = __floats2bfloat162_rn(fabsf(fav[2 * j] - wv[2 * j]),
                                          fabsf(fav[2 * j + 1] - wv[2 * j + 1]));
        }
        *(uint4*)(xrow + 256 + c) = W;
        *(uint4*)(xrow + 512 + c) = D;
    }

#pragma unroll
    for (int o = 16; o; o >>= 1) {
        na += __shfl_xor_sync(0xffffffffu, na, o);
#pragma unroll
        for (int s = 0; s < 9; s++) {
            ns[s] += __shfl_xor_sync(0xffffffffu, ns[s], o);
            dt[s] += __shfl_xor_sync(0xffffffffu, dt[s], o);
        }
    }
    if (lane == 0) {
        float sna = fmaxf(sqrtf(na), 1e-12f);
        float dispx = gx - ((px + 0.5f) * (2.f / 128.f) - 1.f);
        float dispy = gy - ((py + 0.5f) * (2.f / 128.f) - 1.f);
        float cfv = cf[p];
        if (!(cfv == cfv)) cfv = 0.f;
        cfv = fminf(fmaxf(cfv, 0.f), 1.f);
        xrow[768] = __float2bfloat16(dispx);
        xrow[769] = __float2bfloat16(dispy);
        xrow[770] = __float2bfloat16(cfv);
#pragma unroll
        for (int s = 0; s < 9; s++)
            xrow[771 + s] = __float2bfloat16(dt[s] / (sna * fmaxf(sqrtf(ns[s]), 1e-12f)));
    } else if (lane <= 13) {
        ((uint2*)(xrow + 780))[lane - 1] = make_uint2(0u, 0u);   // zero pad 780..831
    }
}

// ---------------- shared epilogue: per-CTA (sum, sumsq) per channel ----------------
#define STATS_EPILOGUE(ACC, SRED, SRED2, SLOT)                                        \
    {                                                                                 \
        float ps[4][2], pq[4][2];                                                     \
        _Pragma("unroll")                                                             \
        for (int nt = 0; nt < 4; nt++) {                                              \
            float v0 = ACC[0][nt][0], v1 = ACC[0][nt][2],                             \
                  v2 = ACC[1][nt][0], v3 = ACC[1][nt][2];                             \
            ps[nt][0] = v0 + v1 + v2 + v3;                                            \
            pq[nt][0] = v0 * v0 + v1 * v1 + v2 * v2 + v3 * v3;                        \
            float u0 = ACC[0][nt][1], u1 = ACC[0][nt][3],                             \
                  u2 = ACC[1][nt][1], u3 = ACC[1][nt][3];                             \
            ps[nt][1] = u0 + u1 + u2 + u3;                                            \
            pq[nt][1] = u0 * u0 + u1 * u1 + u2 * u2 + u3 * u3;                        \
        }                                                                             \
        _Pragma("unroll")                                                             \
        for (int o = 4; o <= 16; o <<= 1)                                             \
            _Pragma("unroll")                                                         \
            for (int nt = 0; nt < 4; nt++)                                            \
                _Pragma("unroll")                                                     \
                for (int pr = 0; pr < 2; pr++) {                                      \
                    ps[nt][pr] += __shfl_xor_sync(0xffffffffu, ps[nt][pr], o);        \
                    pq[nt][pr] += __shfl_xor_sync(0xffffffffu, pq[nt][pr], o);        \
                }                                                                     \
        if (lane < 4) {                                                               \
            _Pragma("unroll")                                                         \
            for (int nt = 0; nt < 4; nt++)                                            \
                _Pragma("unroll")                                                     \
                for (int pr = 0; pr < 2; pr++) {                                      \
                    SRED[warp][nt * 8 + 2 * lane + pr] = ps[nt][pr];                  \
                    SRED2[warp][nt * 8 + 2 * lane + pr] = pq[nt][pr];                 \
                }                                                                     \
        }                                                                             \
        __syncthreads();                                                              \
        if (tid < 64) {                                                               \
            int wn2 = tid >> 5, j2 = tid & 31;                                        \
            float ssum = 0.f, qsum = 0.f;                                             \
            _Pragma("unroll")                                                         \
            for (int wm2 = 0; wm2 < 4; wm2++) {                                       \
                ssum += SRED[wn2 * 4 + wm2][j2];                                      \
                qsum += SRED2[wn2 * 4 + wm2][j2];                                     \
            }                                                                         \
            g_pcs[(size_t)(SLOT) * 64 + wn2 * 32 + j2] = ssum;                        \
            g_pcs2[(size_t)(SLOT) * 64 + wn2 * 32 + j2] = qsum;                       \
        }                                                                             \
    }

// ---------------- enc1 GEMM: cp.async double-buffered ----------------
#define GEMM_SMEM (2 * 9216 * 2 + 2 * 4608 * 2)
__global__ void __launch_bounds__(256) k_gemm1_mma() {
    extern __shared__ __nv_bfloat16 dyn[];
    __nv_bfloat16* As = dyn;               // [2][128*72]
    __nv_bfloat16* Bs = dyn + 2 * 9216;    // [2][64*72]
    __shared__ float sred[8][32], sred2[8][32];
    int tid = threadIdx.x;
    int warp = tid >> 5, lane = tid & 31;
    int g = lane >> 2, t = lane & 3;
    int wm = warp & 3, wn = warp >> 2;
    float acc[2][4][4];
#pragma unroll
    for (int mt = 0; mt < 2; mt++)
#pragma unroll
        for (int nt = 0; nt < 4; nt++)
#pragma unroll
            for (int j = 0; j < 4; j++) acc[mt][nt][j] = 0.f;

    int pix0 = blockIdx.x * 128;
    int arow = tid >> 1, acol = (tid & 1) * 32;
    const __nv_bfloat16* asrc0 = g_xb + (size_t)(pix0 + arow) * 832 + acol;
    uint32_t adst0 = smem_u32(As + arow * 72 + acol);
    int brow0 = tid >> 3, bseg = (tid & 7) * 8;
    uint32_t bdst0 = smem_u32(Bs + brow0 * 72 + bseg);
    const __nv_bfloat16* bsrc0 = g_w1k + brow0 * 64 + bseg;

    auto load_chunk = [&](int chunk) {
        int buf = chunk & 1;
        uint32_t ad = adst0 + buf * 9216 * 2;
        const __nv_bfloat16* as = asrc0 + chunk * 64;
#pragma unroll
        for (int j = 0; j < 4; j++)
            cp16(ad + j * 16, as + j * 8);
        uint32_t bd = bdst0 + buf * 4608 * 2;
        const __nv_bfloat16* bs = bsrc0 + chunk * 4096;
        cp16(bd, bs);
        cp16(bd + 32 * 72 * 2, bs + 32 * 64);
        cp_commit();
    };

    load_chunk(0);
    for (int chunk = 0; chunk < 13; chunk++) {
        if (chunk < 12) { load_chunk(chunk + 1); cp_wait<1>(); }
        else cp_wait<0>();
        __syncthreads();
        int buf = chunk & 1;
        const __nv_bfloat16* Ab = As + buf * 9216;
        const __nv_bfloat16* Bb = Bs + buf * 4608;
#pragma unroll
        for (int ks = 0; ks < 4; ks++) {
            int k0 = ks * 16;
            uint32_t a[2][4], bb[4][2];
#pragma unroll
            for (int mt = 0; mt < 2; mt++) {
                int row0 = wm * 32 + mt * 16 + g;
                a[mt][0] = *(const uint32_t*)(Ab + row0 * 72 + k0 + 2 * t);
                a[mt][1] = *(const uint32_t*)(Ab + (row0 + 8) * 72 + k0 + 2 * t);
                a[mt][2] = *(const uint32_t*)(Ab + row0 * 72 + k0 + 2 * t + 8);
                a[mt][3] = *(const uint32_t*)(Ab + (row0 + 8) * 72 + k0 + 2 * t + 8);
            }
#pragma unroll
            for (int nt = 0; nt < 4; nt++) {
                int n = wn * 32 + nt * 8 + g;
                bb[nt][0] = *(const uint32_t*)(Bb + n * 72 + k0 + 2 * t);
                bb[nt][1] = *(const uint32_t*)(Bb + n * 72 + k0 + 2 * t + 8);
            }
#pragma unroll
            for (int mt = 0; mt < 2; mt++)
#pragma unroll
                for (int nt = 0; nt < 4; nt++)
                    mma16816(acc[mt][nt], a[mt], bb[nt]);
        }
        __syncthreads();
    }
#pragma unroll
    for (int mt = 0; mt < 2; mt++) {
        int row = wm * 32 + mt * 16 + g;
#pragma unroll
        for (int nt = 0; nt < 4; nt++) {
            int col = wn * 32 + nt * 8 + 2 * t;
            float* dst = g_h1 + (size_t)(pix0 + row) * 64 + col;
            *(float2*)dst = make_float2(acc[mt][nt][0], acc[mt][nt][1]);
            *(float2*)(dst + 512) = make_float2(acc[mt][nt][2], acc[mt][nt][3]);
        }
    }
    __syncthreads();
    STATS_EPILOGUE(acc, sred, sred2, blockIdx.x)
}

// ---------------- 3x3 conv: cp.async weights overlapped with GELU halo ----------------
#define CONV_SMEM (180 * 72 * 2 + 9 * 64 * 72 * 2)
__global__ void __launch_bounds__(256) k_conv_mma(int which, int srcsel) {
    extern __shared__ __nv_bfloat16 sm[];
    __nv_bfloat16* halo = sm;                 // [pix 180][72]
    __nv_bfloat16* Bs = sm + 180 * 72;        // [tap 9][64][72]
    __shared__ float sg[64], st[64];
    __shared__ float sred[8][32], sred2[8][32];
    const float* src = srcsel ? g_h2 : g_h1;
    float* dst = srcsel ? g_h1 : g_h2;
    int tid = threadIdx.x;
    int warp = tid >> 5, lane = tid & 31;
    int g = lane >> 2, t = lane & 3;
    int wm = warp & 3, wn = warp >> 2;
    int b = blockIdx.x >> 7;
    int tile = blockIdx.x & 127;
    int y0 = (tile >> 4) * 16, x0 = (tile & 15) * 8;

    // kick off weight DMA first (overlaps with GN scale load + halo GELU fill)
    {
        uint32_t bs0 = smem_u32(Bs);
#pragma unroll
        for (int i = 0; i < 18; i++) {
            int idx = tid + i * 256;      // 4608 segments of 16B
            int tap = idx >> 9, rem = idx & 511;
            int row = rem >> 3, seg = rem & 7;
            cp16(bs0 + (tap * 4608 + row * 72 + seg * 8) * 2,
                 g_wck[which] + tap * 4096 + row * 64 + seg * 8);
        }
        cp_commit();
    }

    if (tid < 64) { sg[tid] = g_gns[b * 64 + tid]; st[tid] = g_gnt[b * 64 + tid]; }
    __syncthreads();

    for (int idx = tid; idx < 1440; idx += 256) {
        int pix = idx >> 3, seg = idx & 7;
        int yy = pix / 10, xx = pix - yy * 10;
        int gy = y0 + yy - 1, gx = x0 + xx - 1;
        uint4 v = make_uint4(0, 0, 0, 0);
        if (gy >= 0 && gy < 128 && gx >= 0 && gx < 128) {
            const float4* sp = (const float4*)(src + (size_t)((b << 14) + (gy << 7) + gx) * 64 + seg * 8);
            float4 r0 = sp[0], r1 = sp[1];
            int cb = seg * 8;
            float o0 = geluf(fmaf(r0.x, sg[cb], st[cb]));
            float o1 = geluf(fmaf(r0.y, sg[cb + 1], st[cb + 1]));
            float o2 = geluf(fmaf(r0.z, sg[cb + 2], st[cb + 2]));
            float o3 = geluf(fmaf(r0.w, sg[cb + 3], st[cb + 3]));
            float o4 = geluf(fmaf(r1.x, sg[cb + 4], st[cb + 4]));
            float o5 = geluf(fmaf(r1.y, sg[cb + 5], st[cb + 5]));
            float o6 = geluf(fmaf(r1.z, sg[cb + 6], st[cb + 6]));
            float o7 = geluf(fmaf(r1.w, sg[cb + 7], st[cb + 7]));
            __nv_bfloat162* vh = (__nv_bfloat162*)&v;
            vh[0] = __floats2bfloat162_rn(o0, o1);
            vh[1] = __floats2bfloat162_rn(o2, o3);
            vh[2] = __floats2bfloat162_rn(o4, o5);
            vh[3] = __floats2bfloat162_rn(o6, o7);
        }
        *(uint4*)(halo + pix * 72 + seg * 8) = v;
    }
    cp_wait<0>();
    __syncthreads();

    float acc[2][4][4];
#pragma unroll
    for (int mt = 0; mt < 2; mt++)
#pragma unroll
        for (int nt = 0; nt < 4; nt++)
#pragma unroll
            for (int j = 0; j < 4; j++) acc[mt][nt][j] = 0.f;

#pragma unroll 1
    for (int tap = 0; tap < 9; tap++) {
        int dy = tap / 3 - 1, dx = tap % 3 - 1;
        const __nv_bfloat16* Bt = Bs + tap * 4608;
#pragma unroll
        for (int ks = 0; ks < 4; ks++) {
            int k0 = ks * 16;
            uint32_t a[2][4], bb[4][2];
#pragma unroll
            for (int mt = 0; mt < 2; mt++) {
                int ry = wm * 4 + mt * 2;
                int p0 = (ry + 1 + dy) * 10 + (g + 1 + dx);
                int p1 = p0 + 10;
                a[mt][0] = *(const uint32_t*)(halo + p0 * 72 + k0 + 2 * t);
                a[mt][1] = *(const uint32_t*)(halo + p1 * 72 + k0 + 2 * t);
                a[mt][2] = *(const uint32_t*)(halo + p0 * 72 + k0 + 2 * t + 8);
                a[mt][3] = *(const uint32_t*)(halo + p1 * 72 + k0 + 2 * t + 8);
            }
#pragma unroll
            for (int nt = 0; nt < 4; nt++) {
                int n = wn * 32 + nt * 8 + g;
                bb[nt][0] = *(const uint32_t*)(Bt + n * 72 + k0 + 2 * t);
                bb[nt][1] = *(const uint32_t*)(Bt + n * 72 + k0 + 2 * t + 8);
            }
#pragma unroll
            for (int mt = 0; mt < 2; mt++)
#pragma unroll
                for (int nt = 0; nt < 4; nt++)
                    mma16816(acc[mt][nt], a[mt], bb[nt]);
        }
    }
#pragma unroll
    for (int mt = 0; mt < 2; mt++) {
        int row = wm * 32 + mt * 16 + g;
        int py = y0 + (row >> 3), px = x0 + (row & 7);
#pragma unroll
        for (int nt = 0; nt < 4; nt++) {
            int col = wn * 32 + nt * 8 + 2 * t;
            float* d1 = dst + (size_t)((b << 14) + (py << 7) + px) * 64 + col;
            *(float2*)d1 = make_float2(acc[mt][nt][0], acc[mt][nt][1]);
            float* d2 = dst + (size_t)((b << 14) + ((py + 1) << 7) + px) * 64 + col;
            *(float2*)d2 = make_float2(acc[mt][nt][2], acc[mt][nt][3]);
        }
    }
    __syncthreads();
    STATS_EPILOGUE(acc, sred, sred2, blockIdx.x)
}

// ---------------- GN stats stage 2: 2 blocks x 512 threads ----------------
__global__ void k_stats2(const float* __restrict__ gam, const float* __restrict__ bet) {
    int b = blockIdx.x;
    int tid = threadIdx.x;            // 512
    int c = tid & 63, sl = tid >> 6;  // sl 0..7
    float s = 0.f, s2 = 0.f;
    int base = b * 128 + sl * 16;
#pragma unroll 4
    for (int i = 0; i < 16; i++) {
        s += g_pcs[(size_t)(base + i) * 64 + c];
        s2 += g_pcs2[(size_t)(base + i) * 64 + c];
    }
    __shared__ float ss[8][64], qq[8][64];
    __shared__ float cs[64], cq[64];
    ss[sl][c] = s; qq[sl][c] = s2;
    __syncthreads();
    if (sl == 0) {
        float S = 0.f, Q = 0.f;
#pragma unroll
        for (int j = 0; j < 8; j++) { S += ss[j][c]; Q += qq[j][c]; }
        cs[c] = S; cq[c] = Q;
    }
    __syncthreads();
    if (sl == 0) {
        float gs = 0.f, gq = 0.f;
        int gb = c & ~7;
#pragma unroll
        for (int j = 0; j < 8; j++) { gs += cs[gb + j]; gq += cq[gb + j]; }
        float mu = gs * (1.f / 131072.f);
        float var = gq * (1.f / 131072.f) - mu * mu;
        float sc = gam[c] * rsqrtf(var + 1e-5f);
        g_gns[b * 64 + c] = sc;
        g_gnt[b * 64 + c] = bet[c] - mu * sc;
    }
}

// ---------------- heads: GN+GELU fused, 3-out conv + epilogue ----------------
__global__ void __launch_bounds__(256) k_heads(const float* __restrict__ dw, const float* __restrict__ db,
                                               const float* __restrict__ cwt, const float* __restrict__ cb,
                                               const float* __restrict__ warp, const float* __restrict__ conf,
                                               float* __restrict__ out) {
    __shared__ float sw[3 * 9 * 64];
    int tid = threadIdx.x;
    for (int idx = tid; idx < 1728; idx += 256) {
        int o = idx / 576, rem = idx - o * 576;
        int tap = rem >> 6, c = rem & 63;
        sw[idx] = (o < 2) ? dw[(o * 64 + c) * 9 + tap] : cwt[c * 9 + tap];
    }
    __syncthreads();
    int wr = tid >> 5, lane = tid & 31;
    int p0 = (blockIdx.x * 8 + wr) * 4;
    int b = p0 >> 14, hw = p0 & 16383;
    int y = hw >> 7, x0 = hw & 127;
    int c2 = lane * 2;
    float s0 = g_gns[b * 64 + c2], s1 = g_gns[b * 64 + c2 + 1];
    float t0 = g_gnt[b * 64 + c2], t1 = g_gnt[b * 64 + c2 + 1];

    float nb[3][6][2];
#pragma unroll
    for (int ry = 0; ry < 3; ry++) {
        int yy = y - 1 + ry;
#pragma unroll
        for (int cx = 0; cx < 6; cx++) {
            int xx = x0 - 1 + cx;
            float v0 = 0.f, v1 = 0.f;
            if (yy >= 0 && yy < 128 && xx >= 0 && xx < 128) {
                float2 h = *(const float2*)(g_h1 + (size_t)((b << 14) + (yy << 7) + xx) * 64 + c2);
                v0 = geluf(fmaf(h.x, s0, t0));
                v1 = geluf(fmaf(h.y, s1, t1));
            }
            nb[ry][cx][0] = v0; nb[ry][cx][1] = v1;
        }
    }
    float acc[4][3];
#pragma unroll
    for (int j = 0; j < 4; j++)
#pragma unroll
        for (int o = 0; o < 3; o++) acc[j][o] = 0.f;
#pragma unroll
    for (int ky = 0; ky < 3; ky++)
#pragma unroll
        for (int kx = 0; kx < 3; kx++) {
            int tap = ky * 3 + kx;
            float w0a = sw[tap * 64 + c2], w0b = sw[tap * 64 + c2 + 1];
            float w1a = sw[576 + tap * 64 + c2], w1b = sw[576 + tap * 64 + c2 + 1];
            float w2a = sw[1152 + tap * 64 + c2], w2b = sw[1152 + tap * 64 + c2 + 1];
#pragma unroll
            for (int j = 0; j < 4; j++) {
                float v0 = nb[ky][j + kx][0], v1 = nb[ky][j + kx][1];
                acc[j][0] += w0a * v0 + w0b * v1;
                acc[j][1] += w1a * v0 + w1b * v1;
                acc[j][2] += w2a * v0 + w2b * v1;
            }
        }
#pragma unroll
    for (int o = 16; o; o >>= 1)
#pragma unroll
        for (int j = 0; j < 4; j++) {
            acc[j][0] += __shfl_xor_sync(0xffffffffu, acc[j][0], o);
            acc[j][1] += __shfl_xor_sync(0xffffffffu, acc[j][1], o);
            acc[j][2] += __shfl_xor_sync(0xffffffffu, acc[j][2], o);
        }
    if (lane < 4) {
        int p = p0 + lane;
        float a0 = acc[lane][0], a1 = acc[lane][1], a2 = acc[lane][2];
        float rx = clean15(warp[2 * p]);
        float ry = clean15(warp[2 * p + 1]);
        float fwx = fminf(fmaxf(rx + tanhf(a0 + db[0]) * 0.0625f, -1.5f), 1.5f);
        float fwy = fminf(fmaxf(ry + tanhf(a1 + db[1]) * 0.0625f, -1.5f), 1.5f);
        float cv = conf[p];
        if (!(cv == cv)) cv = 0.f;
        cv = fminf(fmaxf(cv, 0.f), 1.f);
        float pp = fminf(fmaxf(cv, 1e-4f), 1.f - 1e-4f);
        float base = logf(pp) - log1pf(-pp);
        float lg = base + 0.5f * (a2 + cb[0]);
        float rc = fminf(fmaxf(1.f / (1.f + expf(-lg)), 0.f), 1.f);
        out[2 * p] = fwx;
        out[2 * p + 1] = fwy;
        out[65536 + p] = rc;
        out[98304 + p] = lg;
    }
}

extern "C" void kernel_launch(void* const* d_in, const int* in_sizes, int n_in,
                              void* d_out, int out_size) {
    (void)in_sizes; (void)n_in; (void)out_size;
    const float* fA  = (const float*)d_in[0];
    const float* fB  = (const float*)d_in[1];
    const float* cw  = (const float*)d_in[2];
    const float* cf  = (const float*)d_in[3];
    const float* e1w = (const float*)d_in[4];
    const float* g1g = (const float*)d_in[5];
    const float* g1b = (const float*)d_in[6];
    const float* e2w = (const float*)d_in[7];
    const float* g2g = (const float*)d_in[8];
    const float* g2b = (const float*)d_in[9];
    const float* e3w = (const float*)d_in[10];
    const float* g3g = (const float*)d_in[11];
    const float* g3b = (const float*)d_in[12];
    const float* dw  = (const float*)d_in[13];
    const float* db  = (const float*)d_in[14];
    const float* cwt = (const float*)d_in[15];
    const float* cb  = (const float*)d_in[16];
    float* out = (float*)d_out;

    cudaFuncSetAttribute(k_gemm1_mma, cudaFuncAttributeMaxDynamicSharedMemorySize, GEMM_SMEM);
    cudaFuncSetAttribute(k_conv_mma, cudaFuncAttributeMaxDynamicSharedMemorySize, CONV_SMEM);

    k_transpose<<<dim3(512, 4, 4), dim3(32, 8)>>>(fA, fB);
    k_wprep<<<496, 256>>>(e1w, e2w, e3w);
    k_features<<<4096, 256>>>(cw, cf);
    k_gemm1_mma<<<256, 256, GEMM_SMEM>>>();
    k_stats2<<<2, 512>>>(g1g, g1b);
    k_conv_mma<<<256, 256, CONV_SMEM>>>(0, 0);   // read g_h1 -> g_h2
    k_stats2<<<2, 512>>>(g2g, g2b);
    k_conv_mma<<<256, 256, CONV_SMEM>>>(1, 1);   // read g_h2 -> g_h1
    k_stats2<<<2, 512>>>(g3g, g3b);
    k_heads<<<1024, 256>>>(dw, db, cwt, cb, cw, cf, out);
}

// round 8
// speedup vs baseline: 2.8995x; 1.0181x over previous
#include <cuda_runtime.h>
#include <cuda_bf16.h>
#include <math.h>
#include <stdint.h>

#define HWSZ 16384
#define NPIX 32768
#define CC 256

// ---------------- static device scratch ----------------
__device__ __align__(16) __nv_bfloat16 g_fbT[2 * HWSZ * CC];     // feat_B NHWC bf16
__device__ __align__(16) __nv_bfloat16 g_xb[(size_t)NPIX * 832]; // X features bf16 (780 pad->832)
__device__ __align__(16) __nv_bfloat16 g_w1k[13 * 4096];         // enc1 W [chunk][oc][k64]
__device__ __align__(16) __nv_bfloat16 g_wck[2][9 * 4096];       // conv W [tap][oc][ci]
__device__ __align__(16) float g_h1[(size_t)NPIX * 64];          // raw layer out ping
__device__ __align__(16) float g_h2[(size_t)NPIX * 64];          // raw layer out pong
__device__ float g_gns[128];
__device__ float g_gnt[128];
__device__ float g_pcs[256 * 64];
__device__ float g_pcs2[256 * 64];

__device__ __forceinline__ float clean15(float v) {
    if (!(v == v)) return 0.f;
    return fminf(fmaxf(v, -1.5f), 1.5f);
}
__device__ __forceinline__ float geluf(float z) {
    return 0.5f * z * (1.f + erff(z * 0.70710678118654752f));
}
__device__ __forceinline__ uint32_t smem_u32(const void* p) {
    uint32_t r;
    asm("{ .reg .u64 t; cvta.to.shared.u64 t, %1; cvt.u32.u64 %0, t; }" : "=r"(r) : "l"(p));
    return r;
}
__device__ __forceinline__ void cp16(uint32_t dst, const void* src) {
    asm volatile("cp.async.cg.shared.global [%0], [%1], 16;" :: "r"(dst), "l"(src));
}
__device__ __forceinline__ void cp_commit() {
    asm volatile("cp.async.commit_group;" ::: "memory");
}
template <int N>
__device__ __forceinline__ void cp_wait() {
    asm volatile("cp.async.wait_group %0;" :: "n"(N) : "memory");
}

// bf16 HMMA: D(16x8,f32) += A(16x16,bf16) * B(8x16,bf16)^T
__device__ __forceinline__ void mma16816(float* d, const uint32_t* a, const uint32_t* b) {
    asm volatile(
        "mma.sync.aligned.m16n8k16.row.col.f32.bf16.bf16.f32 "
        "{%0,%1,%2,%3}, {%4,%5,%6,%7}, {%8,%9}, {%0,%1,%2,%3};"
        : "+f"(d[0]), "+f"(d[1]), "+f"(d[2]), "+f"(d[3])
        : "r"(a[0]), "r"(a[1]), "r"(a[2]), "r"(a[3]), "r"(b[0]), "r"(b[1]));
}

// ---------------- K0: NCHW fp32 -> bf16 transpose ----------------
__global__ void k_transpose(const float* __restrict__ fA, const float* __restrict__ fB) {
    __shared__ float tile[64][33];
    int z = blockIdx.z;
    const float* src = (z >= 2) ? fB : fA;
    int b = z & 1;
    src += (size_t)b * CC * HWSZ;
    __nv_bfloat16* dstbase;
    size_t stride;
    if (z < 2) { dstbase = g_xb + (size_t)(b << 14) * 832; stride = 832; }
    else       { dstbase = g_fbT + ((size_t)(b << 14) << 8); stride = 256; }
    int hw0 = blockIdx.x * 32, c0 = blockIdx.y * 64;
    int tx = threadIdx.x, ty = threadIdx.y;          // (32,8)
#pragma unroll
    for (int i = 0; i < 8; i++) {
        int cr = ty + i * 8;
        tile[cr][tx] = src[(c0 + cr) * HWSZ + hw0 + tx];
    }
    __syncthreads();
#pragma unroll
    for (int i = 0; i < 4; i++) {
        int r = ty + i * 8;
        __nv_bfloat162 v = __floats2bfloat162_rn(tile[2 * tx][r], tile[2 * tx + 1][r]);
        *(__nv_bfloat162*)(dstbase + (size_t)(hw0 + r) * stride + c0 + 2 * tx) = v;
    }
}

// ---------------- weight prep ----------------
__global__ void k_wprep(const float* __restrict__ w1, const float* __restrict__ w2,
                        const float* __restrict__ w3) {
    int blk = blockIdx.x;
    if (blk < 208) {
        int idx = blk * 256 + threadIdx.x;
        if (idx >= 13 * 4096) return;
        int chunk = idx >> 12, rem = idx & 4095;
        int oc = rem >> 6, k = rem & 63;
        int kg = chunk * 64 + k;
        g_w1k[idx] = __float2bfloat16((kg < 780) ? w1[oc * 780 + kg] : 0.f);
    } else {
        int which = (blk < 352) ? 0 : 1;
        const float* w = which ? w3 : w2;
        int idx = (blk - (which ? 352 : 208)) * 256 + threadIdx.x;
        if (idx >= 9 * 4096) return;
        int tap = idx >> 12, rem = idx & 4095;
        int oc = rem >> 6, ci = rem & 63;
        g_wck[which][idx] = __float2bfloat16(w[(oc * 64 + ci) * 9 + tap]);
    }
}

// ---------------- K1: per-pixel features, all 16 corner gathers front-loaded ----------------
__global__ void __launch_bounds__(256) k_features(const float* __restrict__ cw,
                                                  const float* __restrict__ cf) {
    int p = blockIdx.x * 8 + (threadIdx.x >> 5);
    int lane = threadIdx.x & 31;
    int b = p >> 14, hw = p & 16383;
    int py = hw >> 7, px = hw & 127;

    float gx = clean15(cw[2 * p]);
    float gy = clean15(cw[2 * p + 1]);
    float xc = fmaf(gx, 64.f, 63.5f);
    float yc = fmaf(gy, 64.f, 63.5f);
    float x0f = floorf(xc), y0f = floorf(yc);
    float wx = xc - x0f, wy = yc - y0f;
    float iwx = 1.f - wx, iwy = 1.f - wy;
    int x0 = (int)x0f, y0 = (int)y0f;

    __nv_bfloat16* xrow = g_xb + (size_t)p * 832;
    int c = lane * 8;

    // issue all 17 independent 16B loads up front (MLP 17)
    uint4 cU[4][4];
#pragma unroll
    for (int t = 0; t < 4; t++) {
        int cyp = min(max(y0 - 1 + t, 0), 127);
#pragma unroll
        for (int u = 0; u < 4; u++) {
            int cxp = min(max(x0 - 1 + u, 0), 127);
            cU[t][u] = *(const uint4*)(g_fbT + ((((b << 14) + (cyp << 7) + cxp) << 8) + c));
        }
    }
    uint4 faU = *(const uint4*)(xrow + c);

    float fav[8];
    {
        const __nv_bfloat162* h = (const __nv_bfloat162*)&faU;
#pragma unroll
        for (int j = 0; j < 4; j++) {
            float2 f = __bfloat1622float2(h[j]);
            fav[2 * j] = f.x; fav[2 * j + 1] = f.y;
        }
    }
    float na = 0.f, ns[9], dt[9];
#pragma unroll
    for (int s = 0; s < 9; s++) { ns[s] = 0.f; dt[s] = 0.f; }
#pragma unroll
    for (int j = 0; j < 8; j++) na += fav[j] * fav[j];

    float lxp[3][8];
    float wv[8];
#pragma unroll
    for (int t = 0; t < 4; t++) {
        float cv[4][8];
#pragma unroll
        for (int u = 0; u < 4; u++) {
            const __nv_bfloat162* h = (const __nv_bfloat162*)&cU[t][u];
#pragma unroll
            for (int j = 0; j < 4; j++) {
                float2 f = __bfloat1622float2(h[j]);
                cv[u][2 * j] = f.x; cv[u][2 * j + 1] = f.y;
            }
        }
        float lx[3][8];
#pragma unroll
        for (int j = 0; j < 8; j++) {
            lx[0][j] = cv[0][j] * iwx + cv[1][j] * wx;
            lx[1][j] = cv[1][j] * iwx + cv[2][j] * wx;
            lx[2][j] = cv[2][j] * iwx + cv[3][j] * wx;
        }
        if (t > 0) {
            int dyrow = t - 1;
#pragma unroll
            for (int i = 0; i < 3; i++) {
                int s = dyrow * 3 + i;
#pragma unroll
                for (int j = 0; j < 8; j++) {
                    float v = lxp[i][j] * iwy + lx[i][j] * wy;
                    ns[s] += v * v;
                    dt[s] += fav[j] * v;
                    if (dyrow == 1 && i == 1) wv[j] = v;
                }
            }
        }
#pragma unroll
        for (int i = 0; i < 3; i++)
#pragma unroll
            for (int j = 0; j < 8; j++) lxp[i][j] = lx[i][j];
    }
    {
        uint4 W, D;
        __nv_bfloat162* wh = (__nv_bfloat162*)&W;
        __nv_bfloat162* dh = (__nv_bfloat162*)&D;
#pragma unroll
        for (int j = 0; j < 4; j++) {
            wh[j] = __floats2bfloat162_rn(wv[2 * j], wv[2 * j + 1]);
            dh[j] = __floats2bfloat162_rn(fabsf(fav[2 * j] - wv[2 * j]),
                                          fabsf(fav[2 * j + 1] - wv[2 * j + 1]));
        }
        *(uint4*)(xrow + 256 + c) = W;
        *(uint4*)(xrow + 512 + c) = D;
    }

#pragma unroll
    for (int o = 16; o; o >>= 1) {
        na += __shfl_xor_sync(0xffffffffu, na, o);
#pragma unroll
        for (int s = 0; s < 9; s++) {
            ns[s] += __shfl_xor_sync(0xffffffffu, ns[s], o);
            dt[s] += __shfl_xor_sync(0xffffffffu, dt[s], o);
        }
    }
    if (lane == 0) {
        float sna = fmaxf(sqrtf(na), 1e-12f);
        float dispx = gx - ((px + 0.5f) * (2.f / 128.f) - 1.f);
        float dispy = gy - ((py + 0.5f) * (2.f / 128.f) - 1.f);
        float cfv = cf[p];
        if (!(cfv == cfv)) cfv = 0.f;
        cfv = fminf(fmaxf(cfv, 0.f), 1.f);
        xrow[768] = __float2bfloat16(dispx);
        xrow[769] = __float2bfloat16(dispy);
        xrow[770] = __float2bfloat16(cfv);
#pragma unroll
        for (int s = 0; s < 9; s++)
            xrow[771 + s] = __float2bfloat16(dt[s] / (sna * fmaxf(sqrtf(ns[s]), 1e-12f)));
    } else if (lane <= 13) {
        ((uint2*)(xrow + 780))[lane - 1] = make_uint2(0u, 0u);   // zero pad 780..831
    }
}

// ---------------- shared epilogue: per-CTA (sum, sumsq) per channel ----------------
#define STATS_EPILOGUE(ACC, SRED, SRED2, SLOT)                                        \
    {                                                                                 \
        float ps[4][2], pq[4][2];                                                     \
        _Pragma("unroll")                                                             \
        for (int nt = 0; nt < 4; nt++) {                                              \
            float v0 = ACC[0][nt][0], v1 = ACC[0][nt][2],                             \
                  v2 = ACC[1][nt][0], v3 = ACC[1][nt][2];                             \
            ps[nt][0] = v0 + v1 + v2 + v3;                                            \
            pq[nt][0] = v0 * v0 + v1 * v1 + v2 * v2 + v3 * v3;                        \
            float u0 = ACC[0][nt][1], u1 = ACC[0][nt][3],                             \
                  u2 = ACC[1][nt][1], u3 = ACC[1][nt][3];                             \
            ps[nt][1] = u0 + u1 + u2 + u3;                                            \
            pq[nt][1] = u0 * u0 + u1 * u1 + u2 * u2 + u3 * u3;                        \
        }                                                                             \
        _Pragma("unroll")                                                             \
        for (int o = 4; o <= 16; o <<= 1)                                             \
            _Pragma("unroll")                                                         \
            for (int nt = 0; nt < 4; nt++)                                            \
                _Pragma("unroll")                                                     \
                for (int pr = 0; pr < 2; pr++) {                                      \
                    ps[nt][pr] += __shfl_xor_sync(0xffffffffu, ps[nt][pr], o);        \
                    pq[nt][pr] += __shfl_xor_sync(0xffffffffu, pq[nt][pr], o);        \
                }                                                                     \
        if (lane < 4) {                                                               \
            _Pragma("unroll")                                                         \
            for (int nt = 0; nt < 4; nt++)                                            \
                _Pragma("unroll")                                                     \
                for (int pr = 0; pr < 2; pr++) {                                      \
                    SRED[warp][nt * 8 + 2 * lane + pr] = ps[nt][pr];                  \
                    SRED2[warp][nt * 8 + 2 * lane + pr] = pq[nt][pr];                 \
                }                                                                     \
        }                                                                             \
        __syncthreads();                                                              \
        if (tid < 64) {                                                               \
            int wn2 = tid >> 5, j2 = tid & 31;                                        \
            float ssum = 0.f, qsum = 0.f;                                             \
            _Pragma("unroll")                                                         \
            for (int wm2 = 0; wm2 < 4; wm2++) {                                       \
                ssum += SRED[wn2 * 4 + wm2][j2];                                      \
                qsum += SRED2[wn2 * 4 + wm2][j2];                                     \
            }                                                                         \
            g_pcs[(size_t)(SLOT) * 64 + wn2 * 32 + j2] = ssum;                        \
            g_pcs2[(size_t)(SLOT) * 64 + wn2 * 32 + j2] = qsum;                       \
        }                                                                             \
    }

// ---------------- enc1 GEMM: 4-stage cp.async pipeline ----------------
#define GEMM_SMEM (4 * 9216 * 2 + 4 * 4608 * 2)
__global__ void __launch_bounds__(256) k_gemm1_mma() {
    extern __shared__ __nv_bfloat16 dyn[];
    __nv_bfloat16* As = dyn;               // [4][128*72]
    __nv_bfloat16* Bs = dyn + 4 * 9216;    // [4][64*72]
    __shared__ float sred[8][32], sred2[8][32];
    int tid = threadIdx.x;
    int warp = tid >> 5, lane = tid & 31;
    int g = lane >> 2, t = lane & 3;
    int wm = warp & 3, wn = warp >> 2;
    float acc[2][4][4];
#pragma unroll
    for (int mt = 0; mt < 2; mt++)
#pragma unroll
        for (int nt = 0; nt < 4; nt++)
#pragma unroll
            for (int j = 0; j < 4; j++) acc[mt][nt][j] = 0.f;

    int pix0 = blockIdx.x * 128;
    int arow = tid >> 1, acol = (tid & 1) * 32;
    const __nv_bfloat16* asrc0 = g_xb + (size_t)(pix0 + arow) * 832 + acol;
    uint32_t adst0 = smem_u32(As + arow * 72 + acol);
    int brow0 = tid >> 3, bseg = (tid & 7) * 8;
    uint32_t bdst0 = smem_u32(Bs + brow0 * 72 + bseg);
    const __nv_bfloat16* bsrc0 = g_w1k + brow0 * 64 + bseg;

    auto load_chunk = [&](int chunk) {
        int buf = chunk & 3;
        uint32_t ad = adst0 + buf * 9216 * 2;
        const __nv_bfloat16* as = asrc0 + chunk * 64;
#pragma unroll
        for (int j = 0; j < 4; j++)
            cp16(ad + j * 16, as + j * 8);
        uint32_t bd = bdst0 + buf * 4608 * 2;
        const __nv_bfloat16* bs = bsrc0 + chunk * 4096;
        cp16(bd, bs);
        cp16(bd + 32 * 72 * 2, bs + 32 * 64);
    };

    load_chunk(0); cp_commit();
    load_chunk(1); cp_commit();
    load_chunk(2); cp_commit();
    for (int chunk = 0; chunk < 13; chunk++) {
        if (chunk + 3 < 13) load_chunk(chunk + 3);
        cp_commit();                 // empty commits at tail keep group accounting uniform
        cp_wait<3>();
        __syncthreads();
        int buf = chunk & 3;
        const __nv_bfloat16* Ab = As + buf * 9216;
        const __nv_bfloat16* Bb = Bs + buf * 4608;
#pragma unroll
        for (int ks = 0; ks < 4; ks++) {
            int k0 = ks * 16;
            uint32_t a[2][4], bb[4][2];
#pragma unroll
            for (int mt = 0; mt < 2; mt++) {
                int row0 = wm * 32 + mt * 16 + g;
                a[mt][0] = *(const uint32_t*)(Ab + row0 * 72 + k0 + 2 * t);
                a[mt][1] = *(const uint32_t*)(Ab + (row0 + 8) * 72 + k0 + 2 * t);
                a[mt][2] = *(const uint32_t*)(Ab + row0 * 72 + k0 + 2 * t + 8);
                a[mt][3] = *(const uint32_t*)(Ab + (row0 + 8) * 72 + k0 + 2 * t + 8);
            }
#pragma unroll
            for (int nt = 0; nt < 4; nt++) {
                int n = wn * 32 + nt * 8 + g;
                bb[nt][0] = *(const uint32_t*)(Bb + n * 72 + k0 + 2 * t);
                bb[nt][1] = *(const uint32_t*)(Bb + n * 72 + k0 + 2 * t + 8);
            }
#pragma unroll
            for (int mt = 0; mt < 2; mt++)
#pragma unroll
                for (int nt = 0; nt < 4; nt++)
                    mma16816(acc[mt][nt], a[mt], bb[nt]);
        }
        __syncthreads();
    }
#pragma unroll
    for (int mt = 0; mt < 2; mt++) {
        int row = wm * 32 + mt * 16 + g;
#pragma unroll
        for (int nt = 0; nt < 4; nt++) {
            int col = wn * 32 + nt * 8 + 2 * t;
            float* dst = g_h1 + (size_t)(pix0 + row) * 64 + col;
            *(float2*)dst = make_float2(acc[mt][nt][0], acc[mt][nt][1]);
            *(float2*)(dst + 512) = make_float2(acc[mt][nt][2], acc[mt][nt][3]);
        }
    }
    __syncthreads();
    STATS_EPILOGUE(acc, sred, sred2, blockIdx.x)
}

// ---------------- 3x3 conv: cp.async weights overlapped with GELU halo ----------------
#define CONV_SMEM (180 * 72 * 2 + 9 * 64 * 72 * 2)
__global__ void __launch_bounds__(256) k_conv_mma(int which, int srcsel) {
    extern __shared__ __nv_bfloat16 sm[];
    __nv_bfloat16* halo = sm;                 // [pix 180][72]
    __nv_bfloat16* Bs = sm + 180 * 72;        // [tap 9][64][72]
    __shared__ float sg[64], st[64];
    __shared__ float sred[8][32], sred2[8][32];
    const float* src = srcsel ? g_h2 : g_h1;
    float* dst = srcsel ? g_h1 : g_h2;
    int tid = threadIdx.x;
    int warp = tid >> 5, lane = tid & 31;
    int g = lane >> 2, t = lane & 3;
    int wm = warp & 3, wn = warp >> 2;
    int b = blockIdx.x >> 7;
    int tile = blockIdx.x & 127;
    int y0 = (tile >> 4) * 16, x0 = (tile & 15) * 8;

    {
        uint32_t bs0 = smem_u32(Bs);
#pragma unroll
        for (int i = 0; i < 18; i++) {
            int idx = tid + i * 256;
            int tap = idx >> 9, rem = idx & 511;
            int row = rem >> 3, seg = rem & 7;
            cp16(bs0 + (tap * 4608 + row * 72 + seg * 8) * 2,
                 g_wck[which] + tap * 4096 + row * 64 + seg * 8);
        }
        cp_commit();
    }

    if (tid < 64) { sg[tid] = g_gns[b * 64 + tid]; st[tid] = g_gnt[b * 64 + tid]; }
    __syncthreads();

    for (int idx = tid; idx < 1440; idx += 256) {
        int pix = idx >> 3, seg = idx & 7;
        int yy = pix / 10, xx = pix - yy * 10;
        int gy = y0 + yy - 1, gx = x0 + xx - 1;
        uint4 v = make_uint4(0, 0, 0, 0);
        if (gy >= 0 && gy < 128 && gx >= 0 && gx < 128) {
            const float4* sp = (const float4*)(src + (size_t)((b << 14) + (gy << 7) + gx) * 64 + seg * 8);
            float4 r0 = sp[0], r1 = sp[1];
            int cb = seg * 8;
            float o0 = geluf(fmaf(r0.x, sg[cb], st[cb]));
            float o1 = geluf(fmaf(r0.y, sg[cb + 1], st[cb + 1]));
            float o2 = geluf(fmaf(r0.z, sg[cb + 2], st[cb + 2]));
            float o3 = geluf(fmaf(r0.w, sg[cb + 3], st[cb + 3]));
            float o4 = geluf(fmaf(r1.x, sg[cb + 4], st[cb + 4]));
            float o5 = geluf(fmaf(r1.y, sg[cb + 5], st[cb + 5]));
            float o6 = geluf(fmaf(r1.z, sg[cb + 6], st[cb + 6]));
            float o7 = geluf(fmaf(r1.w, sg[cb + 7], st[cb + 7]));
            __nv_bfloat162* vh = (__nv_bfloat162*)&v;
            vh[0] = __floats2bfloat162_rn(o0, o1);
            vh[1] = __floats2bfloat162_rn(o2, o3);
            vh[2] = __floats2bfloat162_rn(o4, o5);
            vh[3] = __floats2bfloat162_rn(o6, o7);
        }
        *(uint4*)(halo + pix * 72 + seg * 8) = v;
    }
    cp_wait<0>();
    __syncthreads();

    float acc[2][4][4];
#pragma unroll
    for (int mt = 0; mt < 2; mt++)
#pragma unroll
        for (int nt = 0; nt < 4; nt++)
#pragma unroll
            for (int j = 0; j < 4; j++) acc[mt][nt][j] = 0.f;

#pragma unroll 1
    for (int tap = 0; tap < 9; tap++) {
        int dy = tap / 3 - 1, dx = tap % 3 - 1;
        const __nv_bfloat16* Bt = Bs + tap * 4608;
#pragma unroll
        for (int ks = 0; ks < 4; ks++) {
            int k0 = ks * 16;
            uint32_t a[2][4], bb[4][2];
#pragma unroll
            for (int mt = 0; mt < 2; mt++) {
                int ry = wm * 4 + mt * 2;
                int p0 = (ry + 1 + dy) * 10 + (g + 1 + dx);
                int p1 = p0 + 10;
                a[mt][0] = *(const uint32_t*)(halo + p0 * 72 + k0 + 2 * t);
                a[mt][1] = *(const uint32_t*)(halo + p1 * 72 + k0 + 2 * t);
                a[mt][2] = *(const uint32_t*)(halo + p0 * 72 + k0 + 2 * t + 8);
                a[mt][3] = *(const uint32_t*)(halo + p1 * 72 + k0 + 2 * t + 8);
            }
#pragma unroll
            for (int nt = 0; nt < 4; nt++) {
                int n = wn * 32 + nt * 8 + g;
                bb[nt][0] = *(const uint32_t*)(Bt + n * 72 + k0 + 2 * t);
                bb[nt][1] = *(const uint32_t*)(Bt + n * 72 + k0 + 2 * t + 8);
            }
#pragma unroll
            for (int mt = 0; mt < 2; mt++)
#pragma unroll
                for (int nt = 0; nt < 4; nt++)
                    mma16816(acc[mt][nt], a[mt], bb[nt]);
        }
    }
#pragma unroll
    for (int mt = 0; mt < 2; mt++) {
        int row = wm * 32 + mt * 16 + g;
        int py = y0 + (row >> 3), px = x0 + (row & 7);
#pragma unroll
        for (int nt = 0; nt < 4; nt++) {
            int col = wn * 32 + nt * 8 + 2 * t;
            float* d1 = dst + (size_t)((b << 14) + (py << 7) + px) * 64 + col;
            *(float2*)d1 = make_float2(acc[mt][nt][0], acc[mt][nt][1]);
            float* d2 = dst + (size_t)((b << 14) + ((py + 1) << 7) + px) * 64 + col;
            *(float2*)d2 = make_float2(acc[mt][nt][2], acc[mt][nt][3]);
        }
    }
    __syncthreads();
    STATS_EPILOGUE(acc, sred, sred2, blockIdx.x)
}

// ---------------- GN stats stage 2 ----------------
__global__ void k_stats2(const float* __restrict__ gam, const float* __restrict__ bet) {
    int b = blockIdx.x;
    int tid = threadIdx.x;            // 512
    int c = tid & 63, sl = tid >> 6;
    float s = 0.f, s2 = 0.f;
    int base = b * 128 + sl * 16;
#pragma unroll 4
    for (int i = 0; i < 16; i++) {
        s += g_pcs[(size_t)(base + i) * 64 + c];
        s2 += g_pcs2[(size_t)(base + i) * 64 + c];
    }
    __shared__ float ss[8][64], qq[8][64];
    __shared__ float cs[64], cq[64];
    ss[sl][c] = s; qq[sl][c] = s2;
    __syncthreads();
    if (sl == 0) {
        float S = 0.f, Q = 0.f;
#pragma unroll
        for (int j = 0; j < 8; j++) { S += ss[j][c]; Q += qq[j][c]; }
        cs[c] = S; cq[c] = Q;
    }
    __syncthreads();
    if (sl == 0) {
        float gs = 0.f, gq = 0.f;
        int gb = c & ~7;
#pragma unroll
        for (int j = 0; j < 8; j++) { gs += cs[gb + j]; gq += cq[gb + j]; }
        float mu = gs * (1.f / 131072.f);
        float var = gq * (1.f / 131072.f) - mu * mu;
        float sc = gam[c] * rsqrtf(var + 1e-5f);
        g_gns[b * 64 + c] = sc;
        g_gnt[b * 64 + c] = bet[c] - mu * sc;
    }
}

// ---------------- heads ----------------
__global__ void __launch_bounds__(256) k_heads(const float* __restrict__ dw, const float* __restrict__ db,
                                               const float* __restrict__ cwt, const float* __restrict__ cb,
                                               const float* __restrict__ warp, const float* __restrict__ conf,
                                               float* __restrict__ out) {
    __shared__ float sw[3 * 9 * 64];
    int tid = threadIdx.x;
    for (int idx = tid; idx < 1728; idx += 256) {
        int o = idx / 576, rem = idx - o * 576;
        int tap = rem >> 6, c = rem & 63;
        sw[idx] = (o < 2) ? dw[(o * 64 + c) * 9 + tap] : cwt[c * 9 + tap];
    }
    __syncthreads();
    int wr = tid >> 5, lane = tid & 31;
    int p0 = (blockIdx.x * 8 + wr) * 4;
    int b = p0 >> 14, hw = p0 & 16383;
    int y = hw >> 7, x0 = hw & 127;
    int c2 = lane * 2;
    float s0 = g_gns[b * 64 + c2], s1 = g_gns[b * 64 + c2 + 1];
    float t0 = g_gnt[b * 64 + c2], t1 = g_gnt[b * 64 + c2 + 1];

    float nb[3][6][2];
#pragma unroll
    for (int ry = 0; ry < 3; ry++) {
        int yy = y - 1 + ry;
#pragma unroll
        for (int cx = 0; cx < 6; cx++) {
            int xx = x0 - 1 + cx;
            float v0 = 0.f, v1 = 0.f;
            if (yy >= 0 && yy < 128 && xx >= 0 && xx < 128) {
                float2 h = *(const float2*)(g_h1 + (size_t)((b << 14) + (yy << 7) + xx) * 64 + c2);
                v0 = geluf(fmaf(h.x, s0, t0));
                v1 = geluf(fmaf(h.y, s1, t1));
            }
            nb[ry][cx][0] = v0; nb[ry][cx][1] = v1;
        }
    }
    float acc[4][3];
#pragma unroll
    for (int j = 0; j < 4; j++)
#pragma unroll
        for (int o = 0; o < 3; o++) acc[j][o] = 0.f;
#pragma unroll
    for (int ky = 0; ky < 3; ky++)
#pragma unroll
        for (int kx = 0; kx < 3; kx++) {
            int tap = ky * 3 + kx;
            float w0a = sw[tap * 64 + c2], w0b = sw[tap * 64 + c2 + 1];
            float w1a = sw[576 + tap * 64 + c2], w1b = sw[576 + tap * 64 + c2 + 1];
            float w2a = sw[1152 + tap * 64 + c2], w2b = sw[1152 + tap * 64 + c2 + 1];
#pragma unroll
            for (int j = 0; j < 4; j++) {
                float v0 = nb[ky][j + kx][0], v1 = nb[ky][j + kx][1];
                acc[j][0] += w0a * v0 + w0b * v1;
                acc[j][1] += w1a * v0 + w1b * v1;
                acc[j][2] += w2a * v0 + w2b * v1;
            }
        }
#pragma unroll
    for (int o = 16; o; o >>= 1)
#pragma unroll
        for (int j = 0; j < 4; j++) {
            acc[j][0] += __shfl_xor_sync(0xffffffffu, acc[j][0], o);
            acc[j][1] += __shfl_xor_sync(0xffffffffu, acc[j][1], o);
            acc[j][2] += __shfl_xor_sync(0xffffffffu, acc[j][2], o);
        }
    if (lane < 4) {
        int p = p0 + lane;
        float a0 = acc[lane][0], a1 = acc[lane][1], a2 = acc[lane][2];
        float rx = clean15(warp[2 * p]);
        float ry = clean15(warp[2 * p + 1]);
        float fwx = fminf(fmaxf(rx + tanhf(a0 + db[0]) * 0.0625f, -1.5f), 1.5f);
        float fwy = fminf(fmaxf(ry + tanhf(a1 + db[1]) * 0.0625f, -1.5f), 1.5f);
        float cv = conf[p];
        if (!(cv == cv)) cv = 0.f;
        cv = fminf(fmaxf(cv, 0.f), 1.f);
        float pp = fminf(fmaxf(cv, 1e-4f), 1.f - 1e-4f);
        float base = logf(pp) - log1pf(-pp);
        float lg = base + 0.5f * (a2 + cb[0]);
        float rc = fminf(fmaxf(1.f / (1.f + expf(-lg)), 0.f), 1.f);
        out[2 * p] = fwx;
        out[2 * p + 1] = fwy;
        out[65536 + p] = rc;
        out[98304 + p] = lg;
    }
}

extern "C" void kernel_launch(void* const* d_in, const int* in_sizes, int n_in,
                              void* d_out, int out_size) {
    (void)in_sizes; (void)n_in; (void)out_size;
    const float* fA  = (const float*)d_in[0];
    const float* fB  = (const float*)d_in[1];
    const float* cw  = (const float*)d_in[2];
    const float* cf  = (const float*)d_in[3];
    const float* e1w = (const float*)d_in[4];
    const float* g1g = (const float*)d_in[5];
    const float* g1b = (const float*)d_in[6];
    const float* e2w = (const float*)d_in[7];
    const float* g2g = (const float*)d_in[8];
    const float* g2b = (const float*)d_in[9];
    const float* e3w = (const float*)d_in[10];
    const float* g3g = (const float*)d_in[11];
    const float* g3b = (const float*)d_in[12];
    const float* dw  = (const float*)d_in[13];
    const float* db  = (const float*)d_in[14];
    const float* cwt = (const float*)d_in[15];
    const float* cb  = (const float*)d_in[16];
    float* out = (float*)d_out;

    cudaFuncSetAttribute(k_gemm1_mma, cudaFuncAttributeMaxDynamicSharedMemorySize, GEMM_SMEM);
    cudaFuncSetAttribute(k_conv_mma, cudaFuncAttributeMaxDynamicSharedMemorySize, CONV_SMEM);

    k_transpose<<<dim3(512, 4, 4), dim3(32, 8)>>>(fA, fB);
    k_wprep<<<496, 256>>>(e1w, e2w, e3w);
    k_features<<<4096, 256>>>(cw, cf);
    k_gemm1_mma<<<256, 256, GEMM_SMEM>>>();
    k_stats2<<<2, 512>>>(g1g, g1b);
    k_conv_mma<<<256, 256, CONV_SMEM>>>(0, 0);   // read g_h1 -> g_h2
    k_stats2<<<2, 512>>>(g2g, g2b);
    k_conv_mma<<<256, 256, CONV_SMEM>>>(1, 1);   // read g_h2 -> g_h1
    k_stats2<<<2, 512>>>(g3g, g3b);
    k_heads<<<1024, 256>>>(dw, db, cwt, cb, cw, cf, out);
}